// round 2
// baseline (speedup 1.0000x reference)
#include <cuda_runtime.h>
#include <math.h>

#define NB 4
#define SEQ 2048
#define DM 512
#define NH 8
#define DH 64

// Scratch (allocation-free rule: __device__ globals)
__device__ float g_Q[NB * NH * SEQ * DH];
__device__ float g_K[NB * NH * SEQ * DH];
__device__ float g_V[NB * NH * SEQ * DH];
__device__ float g_ATT[NB * SEQ * DM];

// ---------------------------------------------------------------------------
// GEMM: C[M,512] = A[M,512] @ W[512,512] + bias
// OUT_MODE 0: scatter to split-head layout [(b*NH+h)*SEQ + s]*DH + dh
// OUT_MODE 1: plain row-major [m][n]
// Block: 256 threads, tile 64x64, K-tile 16, 4x4 per-thread register tile.
// ---------------------------------------------------------------------------
template <int OUT_MODE>
__global__ __launch_bounds__(256) void gemm512(
    const float* __restrict__ A, const float* __restrict__ W,
    const float* __restrict__ bias, float* __restrict__ C)
{
    __shared__ __align__(16) float As[16][68];   // As[k][m] (transposed)
    __shared__ __align__(16) float Bs[16][68];   // Bs[k][n]

    const int tid = threadIdx.x;
    const int tx = tid & 15;       // n-tile position
    const int ty = tid >> 4;       // m-tile position
    const int m0 = blockIdx.y * 64;
    const int n0 = blockIdx.x * 64;

    float acc[4][4] = {};

    for (int k0 = 0; k0 < DM; k0 += 16) {
        // Load A tile (64 rows x 16 k), store transposed As[k][m]
        #pragma unroll
        for (int r = 0; r < 4; r++) {
            int m = (tid >> 4) + r * 16;
            int k = tid & 15;
            As[k][m] = A[(size_t)(m0 + m) * DM + (k0 + k)];
        }
        // Load W tile (16 k x 64 n), natural layout, coalesced
        #pragma unroll
        for (int r = 0; r < 4; r++) {
            int k = (tid >> 6) + r * 4;
            int n = tid & 63;
            Bs[k][n] = W[(size_t)(k0 + k) * DM + (n0 + n)];
        }
        __syncthreads();

        #pragma unroll 8
        for (int k = 0; k < 16; k++) {
            float4 a4 = *(const float4*)&As[k][ty * 4];
            float4 b4 = *(const float4*)&Bs[k][tx * 4];
            float av[4] = {a4.x, a4.y, a4.z, a4.w};
            float bv[4] = {b4.x, b4.y, b4.z, b4.w};
            #pragma unroll
            for (int i = 0; i < 4; i++)
                #pragma unroll
                for (int j = 0; j < 4; j++)
                    acc[i][j] = fmaf(av[i], bv[j], acc[i][j]);
        }
        __syncthreads();
    }

    #pragma unroll
    for (int i = 0; i < 4; i++) {
        int m = m0 + ty * 4 + i;
        #pragma unroll
        for (int j = 0; j < 4; j++) {
            int n = n0 + tx * 4 + j;
            float v = acc[i][j] + bias[n];
            if (OUT_MODE == 0) {
                int b = m >> 11;            // / SEQ
                int s = m & (SEQ - 1);
                int h = n >> 6;             // / DH
                int d = n & (DH - 1);
                C[(((size_t)(b * NH + h)) * SEQ + s) * DH + d] = v;
            } else {
                C[(size_t)m * DM + n] = v;
            }
        }
    }
}

// ---------------------------------------------------------------------------
// Flash attention, fp32. One block per (q-tile of 64, b*h).
// 256 threads; per-thread 4x4 tiles for both the score GEMM and the PV GEMM.
// Online softmax with per-row (m, l, alpha) state in shared memory.
// ---------------------------------------------------------------------------
__global__ __launch_bounds__(256) void attn_kernel()
{
    extern __shared__ __align__(16) float sm[];
    float* Qs   = sm;                  // [64][68]  Qs[d][r]   (d-major)
    float* Ks   = Qs + 64 * 68;        // [64][68]  Ks[d][c]   (d-major)
    float* Vs   = Ks + 64 * 68;        // [64][64]  Vs[c][d]   (natural)
    float* Ps   = Vs + 64 * 64;        // [64][68]  Ps[c][r]
    float* m_sh = Ps + 64 * 68;        // [64]
    float* l_sh = m_sh + 64;           // [64]
    float* al_sh = l_sh + 64;          // [64]

    const int tid = threadIdx.x;
    const int tx = tid & 15;
    const int ty = tid >> 4;
    const int bh = blockIdx.y;
    const int q0 = blockIdx.x * 64;

    const float* __restrict__ Qg = g_Q + (size_t)bh * SEQ * DH;
    const float* __restrict__ Kg = g_K + (size_t)bh * SEQ * DH;
    const float* __restrict__ Vg = g_V + (size_t)bh * SEQ * DH;

    // Load Q tile transposed: Qs[d][r]
    #pragma unroll
    for (int it = 0; it < 16; it++) {
        int idx = tid + it * 256;
        int r = idx >> 6, d = idx & 63;
        Qs[d * 68 + r] = Qg[(size_t)(q0 + r) * DH + d];
    }
    if (tid < 64) { m_sh[tid] = -INFINITY; l_sh[tid] = 0.0f; }

    float acc[4][4] = {};
    const float scale = 0.04419417382415922f;   // 1/sqrt(512) (d_model per source)

    for (int kt = 0; kt < SEQ / 64; kt++) {
        __syncthreads();   // previous PV-GEMM done before overwriting Ks/Vs/Ps
        const int c0 = kt * 64;
        #pragma unroll
        for (int it = 0; it < 16; it++) {
            int idx = tid + it * 256;
            int c = idx >> 6, d = idx & 63;
            Ks[d * 68 + c] = Kg[(size_t)(c0 + c) * DH + d];
            Vs[c * 64 + d] = Vg[(size_t)(c0 + c) * DH + d];
        }
        __syncthreads();

        // S = Q K^T  (64x64x64), 4x4 per thread
        float s[4][4] = {};
        #pragma unroll 8
        for (int d = 0; d < 64; d++) {
            float4 a4 = *(const float4*)&Qs[d * 68 + ty * 4];
            float4 b4 = *(const float4*)&Ks[d * 68 + tx * 4];
            float av[4] = {a4.x, a4.y, a4.z, a4.w};
            float bv[4] = {b4.x, b4.y, b4.z, b4.w};
            #pragma unroll
            for (int i = 0; i < 4; i++)
                #pragma unroll
                for (int j = 0; j < 4; j++)
                    s[i][j] = fmaf(av[i], bv[j], s[i][j]);
        }

        // Online softmax per row (row owned by 16 lanes with same ty; xor<16
        // shuffles stay inside the warp since tx == lane & 15)
        #pragma unroll
        for (int i = 0; i < 4; i++) {
            int row = ty * 4 + i;
            float mx = -INFINITY;
            #pragma unroll
            for (int j = 0; j < 4; j++) { s[i][j] *= scale; mx = fmaxf(mx, s[i][j]); }
            mx = fmaxf(mx, __shfl_xor_sync(0xffffffffu, mx, 1));
            mx = fmaxf(mx, __shfl_xor_sync(0xffffffffu, mx, 2));
            mx = fmaxf(mx, __shfl_xor_sync(0xffffffffu, mx, 4));
            mx = fmaxf(mx, __shfl_xor_sync(0xffffffffu, mx, 8));
            float mp = m_sh[row];
            float mn = fmaxf(mp, mx);
            float rs = 0.0f;
            #pragma unroll
            for (int j = 0; j < 4; j++) {
                float p = __expf(s[i][j] - mn);
                s[i][j] = p;
                rs += p;
            }
            rs += __shfl_xor_sync(0xffffffffu, rs, 1);
            rs += __shfl_xor_sync(0xffffffffu, rs, 2);
            rs += __shfl_xor_sync(0xffffffffu, rs, 4);
            rs += __shfl_xor_sync(0xffffffffu, rs, 8);
            if (tx == 0) {
                float al = __expf(mp - mn);
                m_sh[row] = mn;
                l_sh[row] = l_sh[row] * al + rs;
                al_sh[row] = al;
            }
        }

        // Scatter P to shared: Ps[c][r]
        #pragma unroll
        for (int i = 0; i < 4; i++)
            #pragma unroll
            for (int j = 0; j < 4; j++)
                Ps[(tx * 4 + j) * 68 + (ty * 4 + i)] = s[i][j];
        __syncthreads();

        // Rescale accumulators then O += P V  (64x64x64)
        float al[4];
        #pragma unroll
        for (int i = 0; i < 4; i++) al[i] = al_sh[ty * 4 + i];
        #pragma unroll
        for (int i = 0; i < 4; i++)
            #pragma unroll
            for (int j = 0; j < 4; j++)
                acc[i][j] *= al[i];

        #pragma unroll 8
        for (int k = 0; k < 64; k++) {
            float4 a4 = *(const float4*)&Ps[k * 68 + ty * 4];
            float4 b4 = *(const float4*)&Vs[k * 64 + tx * 4];
            float av[4] = {a4.x, a4.y, a4.z, a4.w};
            float bv[4] = {b4.x, b4.y, b4.z, b4.w};
            #pragma unroll
            for (int i = 0; i < 4; i++)
                #pragma unroll
                for (int j = 0; j < 4; j++)
                    acc[i][j] = fmaf(av[i], bv[j], acc[i][j]);
        }
    }

    // Epilogue: normalize and write merged-head layout [b][s][h*64+d]
    const int b = bh >> 3, h = bh & 7;
    #pragma unroll
    for (int i = 0; i < 4; i++) {
        int row = ty * 4 + i;
        float inv = 1.0f / l_sh[row];
        int sglob = q0 + row;
        #pragma unroll
        for (int j = 0; j < 4; j++) {
            int col = h * DH + tx * 4 + j;
            g_ATT[((size_t)(b * SEQ + sglob)) * DM + col] = acc[i][j] * inv;
        }
    }
}

// ---------------------------------------------------------------------------
extern "C" void kernel_launch(void* const* d_in, const int* in_sizes, int n_in,
                              void* d_out, int out_size)
{
    (void)in_sizes; (void)n_in; (void)out_size;
    const float* x  = (const float*)d_in[0];
    const float* Wq = (const float*)d_in[1];
    const float* bq = (const float*)d_in[2];
    const float* Wk = (const float*)d_in[3];
    const float* bk = (const float*)d_in[4];
    const float* Wv = (const float*)d_in[5];
    const float* bv = (const float*)d_in[6];
    const float* Wo = (const float*)d_in[7];
    const float* bo = (const float*)d_in[8];

    float *qp, *kp, *vp, *ap;
    cudaGetSymbolAddress((void**)&qp, g_Q);
    cudaGetSymbolAddress((void**)&kp, g_K);
    cudaGetSymbolAddress((void**)&vp, g_V);
    cudaGetSymbolAddress((void**)&ap, g_ATT);

    dim3 gp(DM / 64, (NB * SEQ) / 64);   // (8, 128)
    gemm512<0><<<gp, 256>>>(x, Wq, bq, qp);
    gemm512<0><<<gp, 256>>>(x, Wk, bk, kp);
    gemm512<0><<<gp, 256>>>(x, Wv, bv, vp);

    size_t shmem = (size_t)(3 * 64 * 68 + 64 * 64 + 3 * 64) * sizeof(float); // 69376 B
    cudaFuncSetAttribute(attn_kernel, cudaFuncAttributeMaxDynamicSharedMemorySize,
                         (int)shmem);
    dim3 ga(SEQ / 64, NB * NH);          // (32, 32)
    attn_kernel<<<ga, 256, shmem>>>();

    gemm512<1><<<gp, 256>>>(ap, Wo, bo, (float*)d_out);
}

// round 3
// speedup vs baseline: 2.4287x; 2.4287x over previous
#include <cuda_runtime.h>
#include <math.h>
#include <stdint.h>

#define NB 4
#define SEQ 2048
#define DM 512
#define NH 8
#define DH 64

// Scratch (allocation-free rule: __device__ globals)
__device__ float g_Q[NB * NH * SEQ * DH];
__device__ float g_K[NB * NH * SEQ * DH];
__device__ float g_V[NB * NH * SEQ * DH];
__device__ float g_ATT[NB * SEQ * DM];

// ---------------------------------------------------------------------------
// helpers
// ---------------------------------------------------------------------------
__device__ __forceinline__ uint32_t f2tf32(float f) {
    uint32_t u;
    asm("cvt.rna.tf32.f32 %0, %1;" : "=r"(u) : "f"(f));
    return u;
}

__device__ __forceinline__ void mma_tf32(float d[4], const uint32_t a[4],
                                         const uint32_t b[2]) {
    asm volatile(
        "mma.sync.aligned.m16n8k8.row.col.f32.tf32.tf32.f32 "
        "{%0,%1,%2,%3}, {%4,%5,%6,%7}, {%8,%9}, {%0,%1,%2,%3};\n"
        : "+f"(d[0]), "+f"(d[1]), "+f"(d[2]), "+f"(d[3])
        : "r"(a[0]), "r"(a[1]), "r"(a[2]), "r"(a[3]), "r"(b[0]), "r"(b[1]));
}

// ---------------------------------------------------------------------------
// Projection GEMM via tf32 MMA.
// C[M,512] = A[M,512] @ W[512,512] + bias
// Block tile 128(M) x 64(N), k-tile 32, 256 threads = 8 warps (4 M x 2 N),
// warp tile 32x32 = 2 m16-tiles x 4 n8-tiles.
// OUT_MODE 0: scatter to split-head [(b*NH+h)*SEQ+s]*DH+d ; 1: row-major.
// ---------------------------------------------------------------------------
#define AST 36   // SMEM stride (words) for [m][k] tiles: banks (4g+t)%32 distinct
template <int OUT_MODE>
__global__ __launch_bounds__(256) void gemm512_mma(
    const float* __restrict__ A, const float* __restrict__ W,
    const float* __restrict__ bias, float* __restrict__ C)
{
    __shared__ __align__(16) uint32_t As[128 * AST];  // As[m][k], k<32
    __shared__ __align__(16) uint32_t Bs[64 * AST];   // Bs[n][k] (W transposed)

    const int tid  = threadIdx.x;
    const int lane = tid & 31;
    const int w    = tid >> 5;
    const int g    = lane >> 2;   // group id (row within fragment)
    const int t    = lane & 3;    // thread-in-group (k / col pos)
    const int wm   = w & 3;       // warp M position (0..3)
    const int wn   = w >> 2;      // warp N position (0..1)
    const int m0   = blockIdx.y * 128;
    const int n0   = blockIdx.x * 64;

    float acc[2][4][4] = {};

    for (int k0 = 0; k0 < DM; k0 += 32) {
        __syncthreads();
        // Load A tile 128x32 (coalesced float4), convert to tf32
        #pragma unroll
        for (int i = 0; i < 4; i++) {
            int idx = tid + i * 256;          // 0..1023
            int m   = idx >> 3;
            int c4  = idx & 7;
            float4 v = *(const float4*)&A[(size_t)(m0 + m) * DM + k0 + c4 * 4];
            uint4 u = make_uint4(f2tf32(v.x), f2tf32(v.y), f2tf32(v.z), f2tf32(v.w));
            *(uint4*)&As[m * AST + c4 * 4] = u;
        }
        // Load W tile 32(k) x 64(n), store transposed Bs[n][k]
        #pragma unroll
        for (int i = 0; i < 2; i++) {
            int idx = tid + i * 256;          // 0..511
            int kk  = idx >> 4;
            int n4  = idx & 15;
            float4 v = *(const float4*)&W[(size_t)(k0 + kk) * DM + n0 + n4 * 4];
            Bs[(n4 * 4 + 0) * AST + kk] = f2tf32(v.x);
            Bs[(n4 * 4 + 1) * AST + kk] = f2tf32(v.y);
            Bs[(n4 * 4 + 2) * AST + kk] = f2tf32(v.z);
            Bs[(n4 * 4 + 3) * AST + kk] = f2tf32(v.w);
        }
        __syncthreads();

        #pragma unroll
        for (int ks = 0; ks < 4; ks++) {
            uint32_t af[2][4], bf[4][2];
            #pragma unroll
            for (int mt = 0; mt < 2; mt++) {
                int rm = wm * 32 + mt * 16;
                af[mt][0] = As[(rm + g) * AST + ks * 8 + t];
                af[mt][1] = As[(rm + g + 8) * AST + ks * 8 + t];
                af[mt][2] = As[(rm + g) * AST + ks * 8 + t + 4];
                af[mt][3] = As[(rm + g + 8) * AST + ks * 8 + t + 4];
            }
            #pragma unroll
            for (int nt = 0; nt < 4; nt++) {
                int nb = wn * 32 + nt * 8 + g;
                bf[nt][0] = Bs[nb * AST + ks * 8 + t];
                bf[nt][1] = Bs[nb * AST + ks * 8 + t + 4];
            }
            #pragma unroll
            for (int mt = 0; mt < 2; mt++)
                #pragma unroll
                for (int nt = 0; nt < 4; nt++)
                    mma_tf32(acc[mt][nt], af[mt], bf[nt]);
        }
    }

    // Epilogue
    #pragma unroll
    for (int mt = 0; mt < 2; mt++) {
        #pragma unroll
        for (int nt = 0; nt < 4; nt++) {
            #pragma unroll
            for (int e = 0; e < 4; e++) {
                int m = m0 + wm * 32 + mt * 16 + g + ((e >> 1) ? 8 : 0);
                int n = n0 + wn * 32 + nt * 8 + 2 * t + (e & 1);
                float v = acc[mt][nt][e] + bias[n];
                if (OUT_MODE == 0) {
                    int b = m >> 11;
                    int s = m & (SEQ - 1);
                    int h = n >> 6;
                    int d = n & (DH - 1);
                    C[(((size_t)(b * NH + h)) * SEQ + s) * DH + d] = v;
                } else {
                    C[(size_t)m * DM + n] = v;
                }
            }
        }
    }
}

// ---------------------------------------------------------------------------
// Flash attention, tf32 MMA. Block = (64 q-rows, one b*h). 256 threads,
// 8 warps in 4(M) x 2(N) grid; warp tile 16x32 for both S and O.
// Softmax row state (m, l, alpha) in registers (threads own fixed rows).
// ---------------------------------------------------------------------------
#define QST 68   // stride for Qs/Ks/Ps: g-major frag loads conflict-free
#define VST 72   // stride for Vs: t-major (k-major) frag loads conflict-free
__global__ __launch_bounds__(256) void attn_mma_kernel()
{
    extern __shared__ __align__(16) uint32_t smu[];
    uint32_t* Qs = smu;                  // [64][QST] tf32, pre-scaled
    uint32_t* Ks = Qs + 64 * QST;        // [64][QST] tf32, Ks[c][d]
    uint32_t* Vs = Ks + 64 * QST;        // [64][VST] tf32, Vs[c][d]
    uint32_t* Ps = Vs + 64 * VST;        // [64][QST] tf32, Ps[q][c]
    float* pm = (float*)(Ps + 64 * QST); // [2][64] partial row max
    float* ps = pm + 128;                // [2][64] partial row sum

    const int tid  = threadIdx.x;
    const int lane = tid & 31;
    const int w    = tid >> 5;
    const int g    = lane >> 2;
    const int t    = lane & 3;
    const int wm   = w & 3;
    const int wn   = w >> 2;
    const int bh   = blockIdx.y;
    const int q0   = blockIdx.x * 64;

    const float* __restrict__ Qg = g_Q + (size_t)bh * SEQ * DH;
    const float* __restrict__ Kg = g_K + (size_t)bh * SEQ * DH;
    const float* __restrict__ Vg = g_V + (size_t)bh * SEQ * DH;

    const float scale = 0.04419417382415922f;  // 1/sqrt(512)

    // Load Q tile (64x64), pre-scale, convert tf32
    #pragma unroll
    for (int i = 0; i < 4; i++) {
        int idx = tid + i * 256;
        int r = idx >> 4, d4 = idx & 15;
        float4 v = *(const float4*)&Qg[(size_t)(q0 + r) * DH + d4 * 4];
        uint4 u = make_uint4(f2tf32(v.x * scale), f2tf32(v.y * scale),
                             f2tf32(v.z * scale), f2tf32(v.w * scale));
        *(uint4*)&Qs[r * QST + d4 * 4] = u;
    }

    const int r0 = wm * 16 + g;    // this thread's two fragment rows
    const int r1 = r0 + 8;
    float m_r0 = -INFINITY, m_r1 = -INFINITY;
    float l_r0 = 0.0f, l_r1 = 0.0f;
    float o[4][4] = {};

    for (int kt = 0; kt < SEQ / 64; kt++) {
        __syncthreads();   // protect Ks/Vs/Ps from previous iteration
        const int c0 = kt * 64;
        #pragma unroll
        for (int i = 0; i < 4; i++) {
            int idx = tid + i * 256;
            int c = idx >> 4, d4 = idx & 15;
            float4 kv = *(const float4*)&Kg[(size_t)(c0 + c) * DH + d4 * 4];
            float4 vv = *(const float4*)&Vg[(size_t)(c0 + c) * DH + d4 * 4];
            *(uint4*)&Ks[c * QST + d4 * 4] =
                make_uint4(f2tf32(kv.x), f2tf32(kv.y), f2tf32(kv.z), f2tf32(kv.w));
            *(uint4*)&Vs[c * VST + d4 * 4] =
                make_uint4(f2tf32(vv.x), f2tf32(vv.y), f2tf32(vv.z), f2tf32(vv.w));
        }
        __syncthreads();

        // ---- S = (Q*scale) K^T : warp tile 16x32, k = 64 ----
        float s[4][4] = {};
        #pragma unroll
        for (int ks = 0; ks < 8; ks++) {
            uint32_t af[4];
            int rm = wm * 16;
            af[0] = Qs[(rm + g) * QST + ks * 8 + t];
            af[1] = Qs[(rm + g + 8) * QST + ks * 8 + t];
            af[2] = Qs[(rm + g) * QST + ks * 8 + t + 4];
            af[3] = Qs[(rm + g + 8) * QST + ks * 8 + t + 4];
            #pragma unroll
            for (int nt = 0; nt < 4; nt++) {
                uint32_t bf[2];
                int cb = wn * 32 + nt * 8 + g;
                bf[0] = Ks[cb * QST + ks * 8 + t];
                bf[1] = Ks[cb * QST + ks * 8 + t + 4];
                mma_tf32(s[nt], af, bf);
            }
        }

        // ---- row max (this warp's 32 cols), exchange across n-halves ----
        float mx0 = -INFINITY, mx1 = -INFINITY;
        #pragma unroll
        for (int nt = 0; nt < 4; nt++) {
            mx0 = fmaxf(mx0, fmaxf(s[nt][0], s[nt][1]));
            mx1 = fmaxf(mx1, fmaxf(s[nt][2], s[nt][3]));
        }
        mx0 = fmaxf(mx0, __shfl_xor_sync(0xffffffffu, mx0, 1));
        mx0 = fmaxf(mx0, __shfl_xor_sync(0xffffffffu, mx0, 2));
        mx1 = fmaxf(mx1, __shfl_xor_sync(0xffffffffu, mx1, 1));
        mx1 = fmaxf(mx1, __shfl_xor_sync(0xffffffffu, mx1, 2));
        if (t == 0) { pm[wn * 64 + r0] = mx0; pm[wn * 64 + r1] = mx1; }
        __syncthreads();

        float mn0 = fmaxf(m_r0, fmaxf(pm[r0], pm[64 + r0]));
        float mn1 = fmaxf(m_r1, fmaxf(pm[r1], pm[64 + r1]));

        // ---- p = exp(s - mn); write P (tf32) to shared; partial sums ----
        float rs0 = 0.0f, rs1 = 0.0f;
        #pragma unroll
        for (int nt = 0; nt < 4; nt++) {
            float p0 = __expf(s[nt][0] - mn0);
            float p1 = __expf(s[nt][1] - mn0);
            float p2 = __expf(s[nt][2] - mn1);
            float p3 = __expf(s[nt][3] - mn1);
            rs0 += p0 + p1;
            rs1 += p2 + p3;
            int cb = wn * 32 + nt * 8 + 2 * t;
            *(uint2*)&Ps[r0 * QST + cb] = make_uint2(f2tf32(p0), f2tf32(p1));
            *(uint2*)&Ps[r1 * QST + cb] = make_uint2(f2tf32(p2), f2tf32(p3));
        }
        rs0 += __shfl_xor_sync(0xffffffffu, rs0, 1);
        rs0 += __shfl_xor_sync(0xffffffffu, rs0, 2);
        rs1 += __shfl_xor_sync(0xffffffffu, rs1, 1);
        rs1 += __shfl_xor_sync(0xffffffffu, rs1, 2);
        if (t == 0) { ps[wn * 64 + r0] = rs0; ps[wn * 64 + r1] = rs1; }
        __syncthreads();

        // ---- update row state (registers), rescale O ----
        float al0 = __expf(m_r0 - mn0);
        float al1 = __expf(m_r1 - mn1);
        m_r0 = mn0; m_r1 = mn1;
        l_r0 = l_r0 * al0 + ps[r0] + ps[64 + r0];
        l_r1 = l_r1 * al1 + ps[r1] + ps[64 + r1];
        #pragma unroll
        for (int nt = 0; nt < 4; nt++) {
            o[nt][0] *= al0; o[nt][1] *= al0;
            o[nt][2] *= al1; o[nt][3] *= al1;
        }

        // ---- O += P V : warp tile 16x32 over k = 64 ----
        #pragma unroll
        for (int ks = 0; ks < 8; ks++) {
            uint32_t af[4];
            int rm = wm * 16;
            af[0] = Ps[(rm + g) * QST + ks * 8 + t];
            af[1] = Ps[(rm + g + 8) * QST + ks * 8 + t];
            af[2] = Ps[(rm + g) * QST + ks * 8 + t + 4];
            af[3] = Ps[(rm + g + 8) * QST + ks * 8 + t + 4];
            #pragma unroll
            for (int nt = 0; nt < 4; nt++) {
                uint32_t bf[2];
                int db = wn * 32 + nt * 8 + g;
                bf[0] = Vs[(ks * 8 + t) * VST + db];
                bf[1] = Vs[(ks * 8 + t + 4) * VST + db];
                mma_tf32(o[nt], af, bf);
            }
        }
    }

    // ---- epilogue: normalize, write merged-head layout ----
    const int b = bh >> 3, h = bh & 7;
    float inv0 = 1.0f / l_r0;
    float inv1 = 1.0f / l_r1;
    #pragma unroll
    for (int nt = 0; nt < 4; nt++) {
        int col = h * DH + wn * 32 + nt * 8 + 2 * t;
        size_t base0 = ((size_t)(b * SEQ + q0 + r0)) * DM + col;
        size_t base1 = ((size_t)(b * SEQ + q0 + r1)) * DM + col;
        g_ATT[base0]     = o[nt][0] * inv0;
        g_ATT[base0 + 1] = o[nt][1] * inv0;
        g_ATT[base1]     = o[nt][2] * inv1;
        g_ATT[base1 + 1] = o[nt][3] * inv1;
    }
}

// ---------------------------------------------------------------------------
extern "C" void kernel_launch(void* const* d_in, const int* in_sizes, int n_in,
                              void* d_out, int out_size)
{
    (void)in_sizes; (void)n_in; (void)out_size;
    const float* x  = (const float*)d_in[0];
    const float* Wq = (const float*)d_in[1];
    const float* bq = (const float*)d_in[2];
    const float* Wk = (const float*)d_in[3];
    const float* bk = (const float*)d_in[4];
    const float* Wv = (const float*)d_in[5];
    const float* bv = (const float*)d_in[6];
    const float* Wo = (const float*)d_in[7];
    const float* bo = (const float*)d_in[8];

    float *qp, *kp, *vp, *ap;
    cudaGetSymbolAddress((void**)&qp, g_Q);
    cudaGetSymbolAddress((void**)&kp, g_K);
    cudaGetSymbolAddress((void**)&vp, g_V);
    cudaGetSymbolAddress((void**)&ap, g_ATT);

    dim3 gp(DM / 64, (NB * SEQ) / 128);   // (8, 64)
    gemm512_mma<0><<<gp, 256>>>(x, Wq, bq, qp);
    gemm512_mma<0><<<gp, 256>>>(x, Wk, bk, kp);
    gemm512_mma<0><<<gp, 256>>>(x, Wv, bv, vp);

    size_t shmem = (size_t)(3 * 64 * QST + 64 * VST) * sizeof(uint32_t)
                 + 256 * sizeof(float);   // Qs+Ks+Ps + Vs + pm/ps = 71680 B
    static bool attr_set = false;
    if (!attr_set) {
        cudaFuncSetAttribute(attn_mma_kernel,
                             cudaFuncAttributeMaxDynamicSharedMemorySize,
                             (int)shmem);
        attr_set = true;
    }
    dim3 ga(SEQ / 64, NB * NH);           // (32, 32)
    attn_mma_kernel<<<ga, 256, shmem>>>();

    gemm512_mma<1><<<gp, 256>>>(ap, Wo, bo, (float*)d_out);
}

// round 5
// speedup vs baseline: 4.3764x; 1.8019x over previous
#include <cuda_runtime.h>
#include <cuda_fp16.h>
#include <math.h>
#include <stdint.h>

#define NB 4
#define SEQ 2048
#define DM 512
#define NH 8
#define DH 64

// Scratch (allocation-free rule: __device__ globals), f16 intermediates
__device__ __half g_Q[NB * NH * SEQ * DH];
__device__ __half g_K[NB * NH * SEQ * DH];
__device__ __half g_V[NB * NH * SEQ * DH];
__device__ __half g_ATT[NB * SEQ * DM];

// ---------------------------------------------------------------------------
// helpers
// ---------------------------------------------------------------------------
__device__ __forceinline__ uint32_t smem_u32(const void* p) {
    uint32_t a;
    asm("{ .reg .u64 t; cvta.to.shared.u64 t, %1; cvt.u32.u64 %0, t; }"
        : "=r"(a) : "l"(p));
    return a;
}

__device__ __forceinline__ void ldsm_x4(uint32_t r[4], uint32_t addr) {
    asm volatile("ldmatrix.sync.aligned.m8n8.x4.shared.b16 {%0,%1,%2,%3}, [%4];"
                 : "=r"(r[0]), "=r"(r[1]), "=r"(r[2]), "=r"(r[3]) : "r"(addr));
}
__device__ __forceinline__ void ldsm_x4_t(uint32_t r[4], uint32_t addr) {
    asm volatile("ldmatrix.sync.aligned.m8n8.x4.trans.shared.b16 {%0,%1,%2,%3}, [%4];"
                 : "=r"(r[0]), "=r"(r[1]), "=r"(r[2]), "=r"(r[3]) : "r"(addr));
}
__device__ __forceinline__ void stsm_x4(uint32_t addr, uint32_t r0, uint32_t r1,
                                        uint32_t r2, uint32_t r3) {
    asm volatile("stmatrix.sync.aligned.m8n8.x4.shared.b16 [%0], {%1,%2,%3,%4};"
                 :: "r"(addr), "r"(r0), "r"(r1), "r"(r2), "r"(r3) : "memory");
}

__device__ __forceinline__ void mma_f16(float d[4], const uint32_t a[4],
                                        uint32_t b0, uint32_t b1) {
    asm volatile(
        "mma.sync.aligned.m16n8k16.row.col.f32.f16.f16.f32 "
        "{%0,%1,%2,%3}, {%4,%5,%6,%7}, {%8,%9}, {%0,%1,%2,%3};\n"
        : "+f"(d[0]), "+f"(d[1]), "+f"(d[2]), "+f"(d[3])
        : "r"(a[0]), "r"(a[1]), "r"(a[2]), "r"(a[3]), "r"(b0), "r"(b1));
}

__device__ __forceinline__ uint32_t h2u(__half2 h) {
    return *reinterpret_cast<uint32_t*>(&h);
}

// 16B chunk loader: f32 source converts to f16, f16 source passes through
__device__ __forceinline__ uint4 ld_chunk(const float* p) {
    float4 v0 = *(const float4*)p;
    float4 v1 = *(const float4*)(p + 4);
    return make_uint4(h2u(__floats2half2_rn(v0.x, v0.y)),
                      h2u(__floats2half2_rn(v0.z, v0.w)),
                      h2u(__floats2half2_rn(v1.x, v1.y)),
                      h2u(__floats2half2_rn(v1.z, v1.w)));
}
__device__ __forceinline__ uint4 ld_chunk(const __half* p) {
    return *(const uint4*)p;
}

__device__ __forceinline__ void st_out(float* C, size_t i, float v) { C[i] = v; }
__device__ __forceinline__ void st_out(__half* C, size_t i, float v) {
    C[i] = __float2half(v);
}

// swizzled byte offset within a 64x64 f16 tile (128B rows)
#define SWZ(row, ch) ((row) * 128 + ((((uint32_t)(ch)) << 4) ^ ((((uint32_t)(row)) & 7) << 4)))

// ---------------------------------------------------------------------------
// Projection GEMM, f16 MMA (m16n8k16) with ldmatrix.
// C[M,512] = A[M,512] @ W[512,512] + bias
// Block tile 128(M) x 64(N), k-tile 64, 256 threads = 8 warps (4M x 2N),
// warp tile 32x32. OUT_MODE 0: scatter split-head; 1: row-major.
// ---------------------------------------------------------------------------
template <int OUT_MODE, typename TIN, typename TOUT>
__global__ __launch_bounds__(256) void gemm512_f16(
    const TIN* __restrict__ A, const float* __restrict__ W,
    const float* __restrict__ bias, TOUT* __restrict__ C)
{
    __shared__ __align__(128) unsigned char sm[24576];  // As 16K + Bs 8K
    const uint32_t AO = smem_u32(sm);
    const uint32_t BO = AO + 16384;

    const int tid  = threadIdx.x;
    const int lane = tid & 31;
    const int w    = tid >> 5;
    const int g    = lane >> 2;
    const int t    = lane & 3;
    const int wm   = w & 3;
    const int wn   = w >> 2;
    const int m0   = blockIdx.y * 128;
    const int n0   = blockIdx.x * 64;

    float acc[2][4][4] = {};

    // precomputed fragment addressing pieces
    const int a_rl   = lane & 15;            // + wm*32 + mt*16
    const int a_kch  = lane >> 4;            // + 2*ks
    const int b_rl   = ((lane >> 3) & 1) * 8 + (lane & 7);  // + ks*16
    const int b_ch   = wn * 4 + (lane >> 4); // + np*2
    const uint32_t b_swz = ((uint32_t)(b_rl & 7)) << 4;

    for (int k0 = 0; k0 < DM; k0 += 64) {
        __syncthreads();
        // A tile 128x64 -> f16 swizzled
        #pragma unroll
        for (int i = 0; i < 4; i++) {
            int idx = tid + i * 256;
            int row = idx >> 3, ch = idx & 7;
            uint4 v = ld_chunk(A + (size_t)(m0 + row) * DM + k0 + ch * 8);
            *(uint4*)(sm + SWZ(row, ch)) = v;
        }
        // B tile 64(k) x 64(n), natural k-major
        #pragma unroll
        for (int i = 0; i < 2; i++) {
            int idx = tid + i * 256;
            int row = idx >> 3, ch = idx & 7;
            uint4 v = ld_chunk(W + (size_t)(k0 + row) * DM + n0 + ch * 8);
            *(uint4*)(sm + 16384 + SWZ(row, ch)) = v;
        }
        __syncthreads();

        #pragma unroll
        for (int ks = 0; ks < 4; ks++) {
            uint32_t a[2][4];
            #pragma unroll
            for (int mt = 0; mt < 2; mt++) {
                int ar = wm * 32 + mt * 16 + a_rl;
                ldsm_x4(a[mt], AO + ar * 128 +
                        ((((uint32_t)(2 * ks + a_kch)) << 4) ^ (((uint32_t)(ar & 7)) << 4)));
            }
            #pragma unroll
            for (int np = 0; np < 2; np++) {
                int br = ks * 16 + b_rl;
                uint32_t bv[4];
                ldsm_x4_t(bv, BO + br * 128 +
                          ((((uint32_t)(b_ch + np * 2)) << 4) ^ b_swz));
                #pragma unroll
                for (int mt = 0; mt < 2; mt++) {
                    mma_f16(acc[mt][np * 2],     a[mt], bv[0], bv[1]);
                    mma_f16(acc[mt][np * 2 + 1], a[mt], bv[2], bv[3]);
                }
            }
        }
    }

    // Epilogue
    #pragma unroll
    for (int mt = 0; mt < 2; mt++) {
        #pragma unroll
        for (int nt = 0; nt < 4; nt++) {
            #pragma unroll
            for (int e = 0; e < 4; e++) {
                int m = m0 + wm * 32 + mt * 16 + g + ((e >> 1) ? 8 : 0);
                int n = n0 + wn * 32 + nt * 8 + 2 * t + (e & 1);
                float v = acc[mt][nt][e] + bias[n];
                if (OUT_MODE == 0) {
                    int b = m >> 11;
                    int s = m & (SEQ - 1);
                    int h = n >> 6;
                    int d = n & (DH - 1);
                    st_out(C, (((size_t)(b * NH + h)) * SEQ + s) * DH + d, v);
                } else {
                    st_out(C, (size_t)m * DM + n, v);
                }
            }
        }
    }
}

// ---------------------------------------------------------------------------
// Flash attention, f16 MMA. Block = (64 q-rows, one b*h). 256 threads,
// 8 warps 4(M) x 2(N); warp tile 16x32 for S and O.
// SMEM: Qs/Ks/Vs/Ps 64x64 f16 swizzled (8KB each) + pm/ps partials.
// ---------------------------------------------------------------------------
__global__ __launch_bounds__(256) void attn_f16_kernel()
{
    __shared__ __align__(128) unsigned char sm[33792];
    const uint32_t SB = smem_u32(sm);
    const uint32_t QO = SB, KO = SB + 8192, VO = SB + 16384, PO = SB + 24576;
    float* pm = (float*)(sm + 32768);   // [2][64]
    float* ps = (float*)(sm + 33280);   // [2][64]

    const int tid  = threadIdx.x;
    const int lane = tid & 31;
    const int w    = tid >> 5;
    const int t    = lane & 3;
    const int wm   = w & 3;
    const int wn   = w >> 2;
    const int bh   = blockIdx.y;
    const int q0   = blockIdx.x * 64;

    const __half* __restrict__ Qg = g_Q + (size_t)bh * SEQ * DH;
    const __half* __restrict__ Kg = g_K + (size_t)bh * SEQ * DH;
    const __half* __restrict__ Vg = g_V + (size_t)bh * SEQ * DH;

    const float scale = 0.04419417382415922f;  // 1/sqrt(512)

    // Load Q tile 64x64 (pure f16 copy, swizzled)
    #pragma unroll
    for (int i = 0; i < 2; i++) {
        int idx = tid + i * 256;
        int row = idx >> 3, ch = idx & 7;
        *(uint4*)(sm + SWZ(row, ch)) =
            *(const uint4*)(Qg + (size_t)(q0 + row) * DH + ch * 8);
    }

    // fragment addressing (lane-fixed parts)
    const int a_rl  = wm * 16 + (lane & 15);
    const uint32_t a_base = a_rl * 128;
    const uint32_t a_swz  = ((uint32_t)(a_rl & 7)) << 4;
    const int a_kch = lane >> 4;

    const int krow0 = wn * 32 + (lane >> 4) * 8 + (lane & 7);
    const int krow1 = krow0 + 16;
    const uint32_t k_base0 = KO + krow0 * 128, k_swz0 = ((uint32_t)(krow0 & 7)) << 4;
    const uint32_t k_base1 = KO + krow1 * 128, k_swz1 = ((uint32_t)(krow1 & 7)) << 4;
    const int kch = (lane >> 3) & 1;

    const int vrow_off = ((lane >> 3) & 1) * 8 + (lane & 7);   // + ks*16
    const uint32_t v_swz = ((uint32_t)(lane & 7)) << 4;
    const int v_ch = wn * 4 + (lane >> 4);                     // + np*2

    const int srow = wm * 16 + ((lane >> 3) & 1) * 8 + (lane & 7);
    const uint32_t s_base = PO + srow * 128;
    const uint32_t s_swz  = ((uint32_t)(srow & 7)) << 4;

    const int r0 = wm * 16 + (lane >> 2);
    const int r1 = r0 + 8;
    float m_r0 = -INFINITY, m_r1 = -INFINITY;
    float l_r0 = 0.0f, l_r1 = 0.0f;
    float o[4][4] = {};

    for (int kt = 0; kt < SEQ / 64; kt++) {
        __syncthreads();   // protect Ks/Vs/Ps from previous iteration
        const int c0 = kt * 64;
        #pragma unroll
        for (int i = 0; i < 2; i++) {
            int idx = tid + i * 256;
            int row = idx >> 3, ch = idx & 7;
            uint32_t off = SWZ(row, ch);
            *(uint4*)(sm + 8192 + off) =
                *(const uint4*)(Kg + (size_t)(c0 + row) * DH + ch * 8);
            *(uint4*)(sm + 16384 + off) =
                *(const uint4*)(Vg + (size_t)(c0 + row) * DH + ch * 8);
        }
        __syncthreads();

        // ---- S = Q K^T : warp tile 16x32, k = 64 (4 k16 steps) ----
        float s[4][4] = {};
        #pragma unroll
        for (int ks = 0; ks < 4; ks++) {
            uint32_t a[4];
            ldsm_x4(a, QO + a_base +
                    ((((uint32_t)(2 * ks + a_kch)) << 4) ^ a_swz));
            uint32_t ck = ((uint32_t)(2 * ks + kch)) << 4;
            uint32_t b0[4], b1[4];
            ldsm_x4(b0, k_base0 + (ck ^ k_swz0));
            ldsm_x4(b1, k_base1 + (ck ^ k_swz1));
            mma_f16(s[0], a, b0[0], b0[1]);
            mma_f16(s[1], a, b0[2], b0[3]);
            mma_f16(s[2], a, b1[0], b1[1]);
            mma_f16(s[3], a, b1[2], b1[3]);
        }

        // ---- online softmax ----
        float mx0 = -INFINITY, mx1 = -INFINITY;
        #pragma unroll
        for (int nt = 0; nt < 4; nt++) {
            #pragma unroll
            for (int e = 0; e < 4; e++) s[nt][e] *= scale;
            mx0 = fmaxf(mx0, fmaxf(s[nt][0], s[nt][1]));
            mx1 = fmaxf(mx1, fmaxf(s[nt][2], s[nt][3]));
        }
        mx0 = fmaxf(mx0, __shfl_xor_sync(0xffffffffu, mx0, 1));
        mx0 = fmaxf(mx0, __shfl_xor_sync(0xffffffffu, mx0, 2));
        mx1 = fmaxf(mx1, __shfl_xor_sync(0xffffffffu, mx1, 1));
        mx1 = fmaxf(mx1, __shfl_xor_sync(0xffffffffu, mx1, 2));
        if (t == 0) { pm[wn * 64 + r0] = mx0; pm[wn * 64 + r1] = mx1; }
        __syncthreads();

        float mn0 = fmaxf(m_r0, fmaxf(pm[r0], pm[64 + r0]));
        float mn1 = fmaxf(m_r1, fmaxf(pm[r1], pm[64 + r1]));

        float rs0 = 0.0f, rs1 = 0.0f;
        #pragma unroll
        for (int nt = 0; nt < 4; nt++) {
            s[nt][0] = __expf(s[nt][0] - mn0);
            s[nt][1] = __expf(s[nt][1] - mn0);
            s[nt][2] = __expf(s[nt][2] - mn1);
            s[nt][3] = __expf(s[nt][3] - mn1);
            rs0 += s[nt][0] + s[nt][1];
            rs1 += s[nt][2] + s[nt][3];
        }
        // P -> SMEM via stmatrix (f16)
        #pragma unroll
        for (int np2 = 0; np2 < 2; np2++) {
            uint32_t h0 = h2u(__floats2half2_rn(s[np2 * 2][0],     s[np2 * 2][1]));
            uint32_t h1 = h2u(__floats2half2_rn(s[np2 * 2][2],     s[np2 * 2][3]));
            uint32_t h2_ = h2u(__floats2half2_rn(s[np2 * 2 + 1][0], s[np2 * 2 + 1][1]));
            uint32_t h3 = h2u(__floats2half2_rn(s[np2 * 2 + 1][2], s[np2 * 2 + 1][3]));
            stsm_x4(s_base + ((((uint32_t)(wn * 4 + np2 * 2 + (lane >> 4))) << 4) ^ s_swz),
                    h0, h1, h2_, h3);
        }
        rs0 += __shfl_xor_sync(0xffffffffu, rs0, 1);
        rs0 += __shfl_xor_sync(0xffffffffu, rs0, 2);
        rs1 += __shfl_xor_sync(0xffffffffu, rs1, 1);
        rs1 += __shfl_xor_sync(0xffffffffu, rs1, 2);
        if (t == 0) { ps[wn * 64 + r0] = rs0; ps[wn * 64 + r1] = rs1; }
        __syncthreads();

        // ---- update row state, rescale O ----
        float al0 = __expf(m_r0 - mn0);
        float al1 = __expf(m_r1 - mn1);
        m_r0 = mn0; m_r1 = mn1;
        l_r0 = l_r0 * al0 + ps[r0] + ps[64 + r0];
        l_r1 = l_r1 * al1 + ps[r1] + ps[64 + r1];
        #pragma unroll
        for (int nt = 0; nt < 4; nt++) {
            o[nt][0] *= al0; o[nt][1] *= al0;
            o[nt][2] *= al1; o[nt][3] *= al1;
        }

        // ---- O += P V : k = 64 over key dim ----
        #pragma unroll
        for (int ks = 0; ks < 4; ks++) {
            uint32_t a[4];
            ldsm_x4(a, PO + a_base +
                    ((((uint32_t)(2 * ks + a_kch)) << 4) ^ a_swz));
            #pragma unroll
            for (int np = 0; np < 2; np++) {
                int vrow = ks * 16 + vrow_off;
                uint32_t b[4];
                ldsm_x4_t(b, VO + vrow * 128 +
                          ((((uint32_t)(v_ch + np * 2)) << 4) ^ v_swz));
                mma_f16(o[np * 2],     a, b[0], b[1]);
                mma_f16(o[np * 2 + 1], a, b[2], b[3]);
            }
        }
    }

    // ---- epilogue: normalize, write merged-head layout (f16) ----
    const int b = bh >> 3, h = bh & 7;
    float inv0 = 1.0f / l_r0;
    float inv1 = 1.0f / l_r1;
    #pragma unroll
    for (int nt = 0; nt < 4; nt++) {
        int col = h * DH + wn * 32 + nt * 8 + 2 * t;
        size_t i0 = ((size_t)(b * SEQ + q0 + r0)) * DM + col;
        size_t i1 = ((size_t)(b * SEQ + q0 + r1)) * DM + col;
        *(__half2*)&g_ATT[i0] = __floats2half2_rn(o[nt][0] * inv0, o[nt][1] * inv0);
        *(__half2*)&g_ATT[i1] = __floats2half2_rn(o[nt][2] * inv1, o[nt][3] * inv1);
    }
}

// ---------------------------------------------------------------------------
extern "C" void kernel_launch(void* const* d_in, const int* in_sizes, int n_in,
                              void* d_out, int out_size)
{
    (void)in_sizes; (void)n_in; (void)out_size;
    const float* x  = (const float*)d_in[0];
    const float* Wq = (const float*)d_in[1];
    const float* bq = (const float*)d_in[2];
    const float* Wk = (const float*)d_in[3];
    const float* bk = (const float*)d_in[4];
    const float* Wv = (const float*)d_in[5];
    const float* bv = (const float*)d_in[6];
    const float* Wo = (const float*)d_in[7];
    const float* bo = (const float*)d_in[8];

    __half *qp, *kp, *vp, *ap;
    cudaGetSymbolAddress((void**)&qp, g_Q);
    cudaGetSymbolAddress((void**)&kp, g_K);
    cudaGetSymbolAddress((void**)&vp, g_V);
    cudaGetSymbolAddress((void**)&ap, g_ATT);

    dim3 gp(DM / 64, (NB * SEQ) / 128);   // (8, 64)
    gemm512_f16<0, float, __half><<<gp, 256>>>(x, Wq, bq, qp);
    gemm512_f16<0, float, __half><<<gp, 256>>>(x, Wk, bk, kp);
    gemm512_f16<0, float, __half><<<gp, 256>>>(x, Wv, bv, vp);

    dim3 ga(SEQ / 64, NB * NH);           // (32, 32)
    attn_f16_kernel<<<ga, 256>>>();

    gemm512_f16<1, __half, float><<<gp, 256>>>(ap, Wo, bo, (float*)d_out);
}

// round 6
// speedup vs baseline: 5.9003x; 1.3482x over previous
#include <cuda_runtime.h>
#include <cuda_fp16.h>
#include <math.h>
#include <stdint.h>

#define NB 4
#define SEQ 2048
#define DM 512
#define NH 8
#define DH 64

// Scratch (allocation-free rule: __device__ globals), f16 intermediates
__device__ __half g_Q[NB * NH * SEQ * DH];
__device__ __half g_K[NB * NH * SEQ * DH];
__device__ __half g_V[NB * NH * SEQ * DH];
__device__ __half g_ATT[NB * SEQ * DM];

// ---------------------------------------------------------------------------
// helpers
// ---------------------------------------------------------------------------
__device__ __forceinline__ uint32_t smem_u32(const void* p) {
    uint32_t a;
    asm("{ .reg .u64 t; cvta.to.shared.u64 t, %1; cvt.u32.u64 %0, t; }"
        : "=r"(a) : "l"(p));
    return a;
}

__device__ __forceinline__ void ldsm_x4(uint32_t r[4], uint32_t addr) {
    asm volatile("ldmatrix.sync.aligned.m8n8.x4.shared.b16 {%0,%1,%2,%3}, [%4];"
                 : "=r"(r[0]), "=r"(r[1]), "=r"(r[2]), "=r"(r[3]) : "r"(addr));
}
__device__ __forceinline__ void ldsm_x4_t(uint32_t r[4], uint32_t addr) {
    asm volatile("ldmatrix.sync.aligned.m8n8.x4.trans.shared.b16 {%0,%1,%2,%3}, [%4];"
                 : "=r"(r[0]), "=r"(r[1]), "=r"(r[2]), "=r"(r[3]) : "r"(addr));
}
__device__ __forceinline__ void stsm_x4(uint32_t addr, uint32_t r0, uint32_t r1,
                                        uint32_t r2, uint32_t r3) {
    asm volatile("stmatrix.sync.aligned.m8n8.x4.shared.b16 [%0], {%1,%2,%3,%4};"
                 :: "r"(addr), "r"(r0), "r"(r1), "r"(r2), "r"(r3) : "memory");
}

__device__ __forceinline__ void mma_f16(float d[4], const uint32_t a[4],
                                        uint32_t b0, uint32_t b1) {
    asm volatile(
        "mma.sync.aligned.m16n8k16.row.col.f32.f16.f16.f32 "
        "{%0,%1,%2,%3}, {%4,%5,%6,%7}, {%8,%9}, {%0,%1,%2,%3};\n"
        : "+f"(d[0]), "+f"(d[1]), "+f"(d[2]), "+f"(d[3])
        : "r"(a[0]), "r"(a[1]), "r"(a[2]), "r"(a[3]), "r"(b0), "r"(b1));
}

__device__ __forceinline__ uint32_t h2u(__half2 h) {
    return *reinterpret_cast<uint32_t*>(&h);
}

// 16B chunk loader: f32 source converts to f16, f16 source passes through
__device__ __forceinline__ uint4 ld_chunk(const float* p) {
    float4 v0 = *(const float4*)p;
    float4 v1 = *(const float4*)(p + 4);
    return make_uint4(h2u(__floats2half2_rn(v0.x, v0.y)),
                      h2u(__floats2half2_rn(v0.z, v0.w)),
                      h2u(__floats2half2_rn(v1.x, v1.y)),
                      h2u(__floats2half2_rn(v1.z, v1.w)));
}
__device__ __forceinline__ uint4 ld_chunk(const __half* p) {
    return *(const uint4*)p;
}

// swizzled byte offset within a 64-col f16 tile (128B rows)
#define SWZ(row, ch) ((row) * 128 + ((((uint32_t)(ch)) << 4) ^ ((((uint32_t)(row)) & 7) << 4)))

// ---------------------------------------------------------------------------
// Fused QKV projection. Block tile 128(M) x 64(N), 384 threads = 12 warps:
// wq = warp/4 selects the weight (Q/K/V), wm = warp%4 the M position.
// x tile loaded to SMEM ONCE, consumed by all three weights (A L2 traffic /3).
// Warp tile 32(M) x 64(N) of one weight. Register prefetch of next k-tile.
// ---------------------------------------------------------------------------
__global__ __launch_bounds__(384, 1) void qkv_fused(
    const float* __restrict__ x,
    const float* __restrict__ Wq, const float* __restrict__ bq,
    const float* __restrict__ Wk, const float* __restrict__ bk,
    const float* __restrict__ Wv, const float* __restrict__ bv,
    __half* __restrict__ oq, __half* __restrict__ ok_, __half* __restrict__ ov)
{
    __shared__ __align__(128) unsigned char sm[40960];  // A 16K + 3x W 8K
    const uint32_t AO = smem_u32(sm);

    const int tid  = threadIdx.x;
    const int lane = tid & 31;
    const int w    = tid >> 5;        // 0..11
    const int g    = lane >> 2;
    const int t    = lane & 3;
    const int wm   = w & 3;           // M position
    const int wq   = w >> 2;          // weight select (== tid>>7)
    const int gtid = tid & 127;       // thread within weight-group
    const int m0   = blockIdx.y * 128;
    const int n0   = blockIdx.x * 64;

    const float* __restrict__ Wsel = (wq == 0) ? Wq : ((wq == 1) ? Wk : Wv);
    const float* __restrict__ bsel = (wq == 0) ? bq : ((wq == 1) ? bk : bv);
    __half* __restrict__ osel      = (wq == 0) ? oq : ((wq == 1) ? ok_ : ov);

    unsigned char* wsm = sm + 16384 + wq * 8192;
    const uint32_t WO  = AO + 16384 + (uint32_t)wq * 8192;

    const uint32_t sw = ((uint32_t)(lane & 7)) << 4;   // common swizzle xor
    const uint32_t a_off0 = (uint32_t)(wm * 32 + (lane & 15)) * 128;
    const int a_kch = lane >> 4;
    const int b_rl  = ((lane >> 3) & 1) * 8 + (lane & 7);
    const int b_ch0 = lane >> 4;

    float acc[2][8][4] = {};   // [mt][nt][e], 64 regs

    // prologue: prefetch k-tile 0
    uint4 pa[3], pw[4];
    #pragma unroll
    for (int i = 0; i < 3; i++) {
        int idx = tid + i * 384;
        if (idx < 1024)
            pa[i] = ld_chunk(x + (size_t)(m0 + (idx >> 3)) * DM + (idx & 7) * 8);
    }
    #pragma unroll
    for (int i = 0; i < 4; i++) {
        int idx = gtid + i * 128;
        pw[i] = ld_chunk(Wsel + (size_t)(idx >> 3) * DM + n0 + (idx & 7) * 8);
    }

    for (int k0 = 0; k0 < DM; k0 += 64) {
        __syncthreads();
        #pragma unroll
        for (int i = 0; i < 3; i++) {
            int idx = tid + i * 384;
            if (idx < 1024) *(uint4*)(sm + SWZ(idx >> 3, idx & 7)) = pa[i];
        }
        #pragma unroll
        for (int i = 0; i < 4; i++) {
            int idx = gtid + i * 128;
            *(uint4*)(wsm + SWZ(idx >> 3, idx & 7)) = pw[i];
        }
        __syncthreads();

        const int kn = k0 + 64;
        if (kn < DM) {   // prefetch next k-tile under the MMAs
            #pragma unroll
            for (int i = 0; i < 3; i++) {
                int idx = tid + i * 384;
                if (idx < 1024)
                    pa[i] = ld_chunk(x + (size_t)(m0 + (idx >> 3)) * DM + kn + (idx & 7) * 8);
            }
            #pragma unroll
            for (int i = 0; i < 4; i++) {
                int idx = gtid + i * 128;
                pw[i] = ld_chunk(Wsel + (size_t)(kn + (idx >> 3)) * DM + n0 + (idx & 7) * 8);
            }
        }

        #pragma unroll
        for (int ks = 0; ks < 4; ks++) {
            uint32_t a[2][4];
            #pragma unroll
            for (int mt = 0; mt < 2; mt++)
                ldsm_x4(a[mt], AO + a_off0 + (uint32_t)(mt * 16) * 128 +
                        ((((uint32_t)(2 * ks + a_kch)) << 4) ^ sw));
            #pragma unroll
            for (int np = 0; np < 4; np++) {
                uint32_t bv4[4];
                ldsm_x4_t(bv4, WO + (uint32_t)(ks * 16 + b_rl) * 128 +
                          ((((uint32_t)(b_ch0 + np * 2)) << 4) ^ sw));
                #pragma unroll
                for (int mt = 0; mt < 2; mt++) {
                    mma_f16(acc[mt][np * 2],     a[mt], bv4[0], bv4[1]);
                    mma_f16(acc[mt][np * 2 + 1], a[mt], bv4[2], bv4[3]);
                }
            }
        }
    }

    // epilogue: bias + scatter to split-head layout (pairwise f16 stores)
    #pragma unroll
    for (int mt = 0; mt < 2; mt++) {
        #pragma unroll
        for (int nt = 0; nt < 8; nt++) {
            #pragma unroll
            for (int eh = 0; eh < 2; eh++) {
                int m = m0 + wm * 32 + mt * 16 + g + eh * 8;
                int n = n0 + nt * 8 + 2 * t;
                float v0 = acc[mt][nt][eh * 2]     + bsel[n];
                float v1 = acc[mt][nt][eh * 2 + 1] + bsel[n + 1];
                int b = m >> 11;
                int s = m & (SEQ - 1);
                int h = n >> 6;
                int d = n & (DH - 1);
                *(__half2*)&osel[(((size_t)(b * NH + h)) * SEQ + s) * DH + d] =
                    __floats2half2_rn(v0, v1);
            }
        }
    }
}

// ---------------------------------------------------------------------------
// Output projection GEMM, f16 MMA (m16n8k16). Block 128x64, 256 threads,
// 8 warps (4M x 2N), warp tile 32x32. Row-major f32 output.
// ---------------------------------------------------------------------------
__global__ __launch_bounds__(256, 2) void gemm_out(
    const __half* __restrict__ A, const float* __restrict__ W,
    const float* __restrict__ bias, float* __restrict__ C)
{
    __shared__ __align__(128) unsigned char sm[24576];  // As 16K + Bs 8K
    const uint32_t AO = smem_u32(sm);
    const uint32_t BO = AO + 16384;

    const int tid  = threadIdx.x;
    const int lane = tid & 31;
    const int w    = tid >> 5;
    const int g    = lane >> 2;
    const int t    = lane & 3;
    const int wm   = w & 3;
    const int wn   = w >> 2;
    const int m0   = blockIdx.y * 128;
    const int n0   = blockIdx.x * 64;

    const uint32_t sw = ((uint32_t)(lane & 7)) << 4;
    const uint32_t a_off0 = (uint32_t)(wm * 32 + (lane & 15)) * 128;
    const int a_kch = lane >> 4;
    const int b_rl  = ((lane >> 3) & 1) * 8 + (lane & 7);
    const int b_ch  = wn * 4 + (lane >> 4);

    float acc[2][4][4] = {};

    for (int k0 = 0; k0 < DM; k0 += 64) {
        __syncthreads();
        #pragma unroll
        for (int i = 0; i < 4; i++) {
            int idx = tid + i * 256;
            int row = idx >> 3, ch = idx & 7;
            *(uint4*)(sm + SWZ(row, ch)) =
                ld_chunk(A + (size_t)(m0 + row) * DM + k0 + ch * 8);
        }
        #pragma unroll
        for (int i = 0; i < 2; i++) {
            int idx = tid + i * 256;
            int row = idx >> 3, ch = idx & 7;
            *(uint4*)(sm + 16384 + SWZ(row, ch)) =
                ld_chunk(W + (size_t)(k0 + row) * DM + n0 + ch * 8);
        }
        __syncthreads();

        #pragma unroll
        for (int ks = 0; ks < 4; ks++) {
            uint32_t a[2][4];
            #pragma unroll
            for (int mt = 0; mt < 2; mt++)
                ldsm_x4(a[mt], AO + a_off0 + (uint32_t)(mt * 16) * 128 +
                        ((((uint32_t)(2 * ks + a_kch)) << 4) ^ sw));
            #pragma unroll
            for (int np = 0; np < 2; np++) {
                uint32_t bv4[4];
                ldsm_x4_t(bv4, BO + (uint32_t)(ks * 16 + b_rl) * 128 +
                          ((((uint32_t)(b_ch + np * 2)) << 4) ^ sw));
                #pragma unroll
                for (int mt = 0; mt < 2; mt++) {
                    mma_f16(acc[mt][np * 2],     a[mt], bv4[0], bv4[1]);
                    mma_f16(acc[mt][np * 2 + 1], a[mt], bv4[2], bv4[3]);
                }
            }
        }
    }

    #pragma unroll
    for (int mt = 0; mt < 2; mt++)
        #pragma unroll
        for (int nt = 0; nt < 4; nt++)
            #pragma unroll
            for (int e = 0; e < 4; e++) {
                int m = m0 + wm * 32 + mt * 16 + g + ((e >> 1) ? 8 : 0);
                int n = n0 + wn * 32 + nt * 8 + 2 * t + (e & 1);
                C[(size_t)m * DM + n] = acc[mt][nt][e] + bias[n];
            }
}

// ---------------------------------------------------------------------------
// Flash attention, f16 MMA. Block = (64 q-rows, one b*h). 128 threads,
// 4 warps (2M x 2N), warp tile 32x32 for S and O (2x fewer LDSM per MMA).
// ---------------------------------------------------------------------------
__global__ __launch_bounds__(128, 4) void attn_f16_v3()
{
    __shared__ __align__(128) unsigned char sm[33792];
    const uint32_t SB = smem_u32(sm);
    const uint32_t QO = SB, KO = SB + 8192, VO = SB + 16384, PO = SB + 24576;
    float* pm = (float*)(sm + 32768);   // [2][64]
    float* ps = (float*)(sm + 33280);   // [2][64]

    const int tid  = threadIdx.x;
    const int lane = tid & 31;
    const int w    = tid >> 5;
    const int g    = lane >> 2;
    const int t    = lane & 3;
    const int wm   = w & 1;
    const int wn   = w >> 1;
    const int bh   = blockIdx.y;
    const int q0   = blockIdx.x * 64;

    const __half* __restrict__ Qg = g_Q + (size_t)bh * SEQ * DH;
    const __half* __restrict__ Kg = g_K + (size_t)bh * SEQ * DH;
    const __half* __restrict__ Vg = g_V + (size_t)bh * SEQ * DH;

    const float scale = 0.04419417382415922f;  // 1/sqrt(512)

    // Load Q tile 64x64 (f16 copy, swizzled)
    #pragma unroll
    for (int i = 0; i < 4; i++) {
        int idx = tid + i * 128;
        int row = idx >> 3, ch = idx & 7;
        *(uint4*)(sm + SWZ(row, ch)) =
            *(const uint4*)(Qg + (size_t)(q0 + row) * DH + ch * 8);
    }

    // lane-fixed addressing pieces (all swizzle XORs equal (lane&7)<<4)
    const uint32_t sw = ((uint32_t)(lane & 7)) << 4;
    const uint32_t a_off0 = (uint32_t)(wm * 32 + (lane & 15)) * 128;
    const int a_kch = lane >> 4;
    const uint32_t k_off0 = KO + (uint32_t)(wn * 32 + (lane >> 4) * 8 + (lane & 7)) * 128;
    const int kch = (lane >> 3) & 1;
    const int vrow_off = ((lane >> 3) & 1) * 8 + (lane & 7);
    const int v_ch = wn * 4 + (lane >> 4);
    const uint32_t s_off0 = PO + (uint32_t)(wm * 32 + ((lane >> 3) & 1) * 8 + (lane & 7)) * 128;
    const int s_ch0 = wn * 4 + (lane >> 4);

    const int r00 = wm * 32 + g;     // rows owned: r00, +8, +16, +24
    float mrow[2][2] = {{-INFINITY, -INFINITY}, {-INFINITY, -INFINITY}};
    float lrow[2][2] = {{0.0f, 0.0f}, {0.0f, 0.0f}};
    float o[2][4][4] = {};

    for (int kt = 0; kt < SEQ / 64; kt++) {
        __syncthreads();   // protect Ks/Vs/Ps from previous iteration
        const int c0 = kt * 64;
        #pragma unroll
        for (int i = 0; i < 4; i++) {
            int idx = tid + i * 128;
            int row = idx >> 3, ch = idx & 7;
            uint32_t off = SWZ(row, ch);
            *(uint4*)(sm + 8192 + off)  = *(const uint4*)(Kg + (size_t)(c0 + row) * DH + ch * 8);
            *(uint4*)(sm + 16384 + off) = *(const uint4*)(Vg + (size_t)(c0 + row) * DH + ch * 8);
        }
        __syncthreads();

        // ---- S = Q K^T : warp tile 32x32, k = 64 ----
        float s[2][4][4] = {};
        #pragma unroll
        for (int ks = 0; ks < 4; ks++) {
            uint32_t ck = ((uint32_t)(2 * ks + kch)) << 4;
            uint32_t bf[2][4];
            ldsm_x4(bf[0], k_off0 + (ck ^ sw));
            ldsm_x4(bf[1], k_off0 + 16 * 128 + (ck ^ sw));
            #pragma unroll
            for (int mt = 0; mt < 2; mt++) {
                uint32_t a[4];
                ldsm_x4(a, QO + a_off0 + (uint32_t)(mt * 16) * 128 +
                        ((((uint32_t)(2 * ks + a_kch)) << 4) ^ sw));
                mma_f16(s[mt][0], a, bf[0][0], bf[0][1]);
                mma_f16(s[mt][1], a, bf[0][2], bf[0][3]);
                mma_f16(s[mt][2], a, bf[1][0], bf[1][1]);
                mma_f16(s[mt][3], a, bf[1][2], bf[1][3]);
            }
        }

        // ---- online softmax: partial max ----
        #pragma unroll
        for (int mt = 0; mt < 2; mt++) {
            float mx0 = -INFINITY, mx1 = -INFINITY;
            #pragma unroll
            for (int nt = 0; nt < 4; nt++) {
                #pragma unroll
                for (int e = 0; e < 4; e++) s[mt][nt][e] *= scale;
                mx0 = fmaxf(mx0, fmaxf(s[mt][nt][0], s[mt][nt][1]));
                mx1 = fmaxf(mx1, fmaxf(s[mt][nt][2], s[mt][nt][3]));
            }
            mx0 = fmaxf(mx0, __shfl_xor_sync(0xffffffffu, mx0, 1));
            mx0 = fmaxf(mx0, __shfl_xor_sync(0xffffffffu, mx0, 2));
            mx1 = fmaxf(mx1, __shfl_xor_sync(0xffffffffu, mx1, 1));
            mx1 = fmaxf(mx1, __shfl_xor_sync(0xffffffffu, mx1, 2));
            if (t == 0) {
                pm[wn * 64 + r00 + mt * 16]     = mx0;
                pm[wn * 64 + r00 + mt * 16 + 8] = mx1;
            }
        }
        __syncthreads();

        float mn[2][2];
        #pragma unroll
        for (int mt = 0; mt < 2; mt++)
            #pragma unroll
            for (int h = 0; h < 2; h++) {
                int r = r00 + mt * 16 + h * 8;
                mn[mt][h] = fmaxf(mrow[mt][h], fmaxf(pm[r], pm[64 + r]));
            }

        // ---- exp, partial sums, P -> SMEM (stmatrix) ----
        #pragma unroll
        for (int mt = 0; mt < 2; mt++) {
            float rs0 = 0.0f, rs1 = 0.0f;
            #pragma unroll
            for (int nt = 0; nt < 4; nt++) {
                s[mt][nt][0] = __expf(s[mt][nt][0] - mn[mt][0]);
                s[mt][nt][1] = __expf(s[mt][nt][1] - mn[mt][0]);
                s[mt][nt][2] = __expf(s[mt][nt][2] - mn[mt][1]);
                s[mt][nt][3] = __expf(s[mt][nt][3] - mn[mt][1]);
                rs0 += s[mt][nt][0] + s[mt][nt][1];
                rs1 += s[mt][nt][2] + s[mt][nt][3];
            }
            #pragma unroll
            for (int np2 = 0; np2 < 2; np2++) {
                uint32_t h0 = h2u(__floats2half2_rn(s[mt][np2 * 2][0],     s[mt][np2 * 2][1]));
                uint32_t h1 = h2u(__floats2half2_rn(s[mt][np2 * 2][2],     s[mt][np2 * 2][3]));
                uint32_t h2_ = h2u(__floats2half2_rn(s[mt][np2 * 2 + 1][0], s[mt][np2 * 2 + 1][1]));
                uint32_t h3 = h2u(__floats2half2_rn(s[mt][np2 * 2 + 1][2], s[mt][np2 * 2 + 1][3]));
                stsm_x4(s_off0 + (uint32_t)(mt * 16) * 128 +
                        ((((uint32_t)(s_ch0 + np2 * 2)) << 4) ^ sw),
                        h0, h1, h2_, h3);
            }
            rs0 += __shfl_xor_sync(0xffffffffu, rs0, 1);
            rs0 += __shfl_xor_sync(0xffffffffu, rs0, 2);
            rs1 += __shfl_xor_sync(0xffffffffu, rs1, 1);
            rs1 += __shfl_xor_sync(0xffffffffu, rs1, 2);
            if (t == 0) {
                ps[wn * 64 + r00 + mt * 16]     = rs0;
                ps[wn * 64 + r00 + mt * 16 + 8] = rs1;
            }
        }
        __syncthreads();

        // ---- update row state, rescale O ----
        float al[2][2];
        #pragma unroll
        for (int mt = 0; mt < 2; mt++)
            #pragma unroll
            for (int h = 0; h < 2; h++) {
                int r = r00 + mt * 16 + h * 8;
                al[mt][h] = __expf(mrow[mt][h] - mn[mt][h]);
                mrow[mt][h] = mn[mt][h];
                lrow[mt][h] = lrow[mt][h] * al[mt][h] + ps[r] + ps[64 + r];
            }
        #pragma unroll
        for (int mt = 0; mt < 2; mt++)
            #pragma unroll
            for (int nt = 0; nt < 4; nt++) {
                o[mt][nt][0] *= al[mt][0]; o[mt][nt][1] *= al[mt][0];
                o[mt][nt][2] *= al[mt][1]; o[mt][nt][3] *= al[mt][1];
            }

        // ---- O += P V : warp tile 32x32, k = 64 keys ----
        #pragma unroll
        for (int ks = 0; ks < 4; ks++) {
            uint32_t bf[2][4];
            #pragma unroll
            for (int np = 0; np < 2; np++)
                ldsm_x4_t(bf[np], VO + (uint32_t)(ks * 16 + vrow_off) * 128 +
                          ((((uint32_t)(v_ch + np * 2)) << 4) ^ (((uint32_t)(lane & 7)) << 4)));
            #pragma unroll
            for (int mt = 0; mt < 2; mt++) {
                uint32_t a[4];
                ldsm_x4(a, PO + a_off0 + (uint32_t)(mt * 16) * 128 +
                        ((((uint32_t)(2 * ks + a_kch)) << 4) ^ sw));
                mma_f16(o[mt][0], a, bf[0][0], bf[0][1]);
                mma_f16(o[mt][1], a, bf[0][2], bf[0][3]);
                mma_f16(o[mt][2], a, bf[1][0], bf[1][1]);
                mma_f16(o[mt][3], a, bf[1][2], bf[1][3]);
            }
        }
    }

    // ---- epilogue: normalize, write merged-head layout (f16) ----
    const int b = bh >> 3, h = bh & 7;
    #pragma unroll
    for (int mt = 0; mt < 2; mt++) {
        float inv0 = 1.0f / lrow[mt][0];
        float inv1 = 1.0f / lrow[mt][1];
        int row0 = q0 + r00 + mt * 16;
        #pragma unroll
        for (int nt = 0; nt < 4; nt++) {
            int col = h * DH + wn * 32 + nt * 8 + 2 * t;
            size_t i0 = ((size_t)(b * SEQ + row0)) * DM + col;
            size_t i1 = ((size_t)(b * SEQ + row0 + 8)) * DM + col;
            *(__half2*)&g_ATT[i0] = __floats2half2_rn(o[mt][nt][0] * inv0, o[mt][nt][1] * inv0);
            *(__half2*)&g_ATT[i1] = __floats2half2_rn(o[mt][nt][2] * inv1, o[mt][nt][3] * inv1);
        }
    }
}

// ---------------------------------------------------------------------------
extern "C" void kernel_launch(void* const* d_in, const int* in_sizes, int n_in,
                              void* d_out, int out_size)
{
    (void)in_sizes; (void)n_in; (void)out_size;
    const float* x  = (const float*)d_in[0];
    const float* Wq = (const float*)d_in[1];
    const float* bq = (const float*)d_in[2];
    const float* Wk = (const float*)d_in[3];
    const float* bk = (const float*)d_in[4];
    const float* Wv = (const float*)d_in[5];
    const float* bv = (const float*)d_in[6];
    const float* Wo = (const float*)d_in[7];
    const float* bo = (const float*)d_in[8];

    __half *qp, *kp, *vp, *ap;
    cudaGetSymbolAddress((void**)&qp, g_Q);
    cudaGetSymbolAddress((void**)&kp, g_K);
    cudaGetSymbolAddress((void**)&vp, g_V);
    cudaGetSymbolAddress((void**)&ap, g_ATT);

    qkv_fused<<<dim3(DM / 64, (NB * SEQ) / 128), 384>>>(
        x, Wq, bq, Wk, bk, Wv, bv, qp, kp, vp);

    attn_f16_v3<<<dim3(SEQ / 64, NB * NH), 128>>>();

    gemm_out<<<dim3(DM / 64, (NB * SEQ) / 128), 256>>>(ap, Wo, bo, (float*)d_out);
}

// round 8
// speedup vs baseline: 6.6503x; 1.1271x over previous
#include <cuda_runtime.h>
#include <cuda_fp16.h>
#include <math.h>
#include <stdint.h>

#define NB 4
#define SEQ 2048
#define DM 512
#define NH 8
#define DH 64

// f16 intermediates / converted operands (allocation-free rule)
__device__ __half g_Q[NB * NH * SEQ * DH];
__device__ __half g_K[NB * NH * SEQ * DH];
__device__ __half g_V[NB * NH * SEQ * DH];
__device__ __half g_ATT[NB * SEQ * DM];
__device__ __half g_Xh[NB * SEQ * DM];
__device__ __half g_Wqkv[DM * 3 * DM];   // [512][1536]: Wq|Wk|Wv columns
__device__ __half g_Woh[DM * DM];
__device__ float  g_bqkv[3 * DM];

// ---------------------------------------------------------------------------
// helpers
// ---------------------------------------------------------------------------
__device__ __forceinline__ uint32_t smem_u32(const void* p) {
    uint32_t a;
    asm("{ .reg .u64 t; cvta.to.shared.u64 t, %1; cvt.u32.u64 %0, t; }"
        : "=r"(a) : "l"(p));
    return a;
}
__device__ __forceinline__ void ldsm_x4(uint32_t r[4], uint32_t addr) {
    asm volatile("ldmatrix.sync.aligned.m8n8.x4.shared.b16 {%0,%1,%2,%3}, [%4];"
                 : "=r"(r[0]), "=r"(r[1]), "=r"(r[2]), "=r"(r[3]) : "r"(addr));
}
__device__ __forceinline__ void ldsm_x4_t(uint32_t r[4], uint32_t addr) {
    asm volatile("ldmatrix.sync.aligned.m8n8.x4.trans.shared.b16 {%0,%1,%2,%3}, [%4];"
                 : "=r"(r[0]), "=r"(r[1]), "=r"(r[2]), "=r"(r[3]) : "r"(addr));
}
__device__ __forceinline__ void stsm_x4(uint32_t addr, uint32_t r0, uint32_t r1,
                                        uint32_t r2, uint32_t r3) {
    asm volatile("stmatrix.sync.aligned.m8n8.x4.shared.b16 [%0], {%1,%2,%3,%4};"
                 :: "r"(addr), "r"(r0), "r"(r1), "r"(r2), "r"(r3) : "memory");
}
__device__ __forceinline__ void mma_f16(float d[4], const uint32_t a[4],
                                        uint32_t b0, uint32_t b1) {
    asm volatile(
        "mma.sync.aligned.m16n8k16.row.col.f32.f16.f16.f32 "
        "{%0,%1,%2,%3}, {%4,%5,%6,%7}, {%8,%9}, {%0,%1,%2,%3};\n"
        : "+f"(d[0]), "+f"(d[1]), "+f"(d[2]), "+f"(d[3])
        : "r"(a[0]), "r"(a[1]), "r"(a[2]), "r"(a[3]), "r"(b0), "r"(b1));
}
__device__ __forceinline__ void cp_async16(uint32_t saddr, const void* g) {
    asm volatile("cp.async.cg.shared.global [%0], [%1], 16;"
                 :: "r"(saddr), "l"(g) : "memory");
}
__device__ __forceinline__ void cp_commit() {
    asm volatile("cp.async.commit_group;" ::: "memory");
}
template <int N>
__device__ __forceinline__ void cp_wait() {
    asm volatile("cp.async.wait_group %0;" :: "n"(N) : "memory");
}
__device__ __forceinline__ uint32_t h2u(__half2 h) {
    return *reinterpret_cast<uint32_t*>(&h);
}
__device__ __forceinline__ uint4 ld_chunk(const float* p) {
    float4 v0 = *(const float4*)p;
    float4 v1 = *(const float4*)(p + 4);
    return make_uint4(h2u(__floats2half2_rn(v0.x, v0.y)),
                      h2u(__floats2half2_rn(v0.z, v0.w)),
                      h2u(__floats2half2_rn(v1.x, v1.y)),
                      h2u(__floats2half2_rn(v1.z, v1.w)));
}

// swizzled byte offset within a 64-col f16 tile (128B rows)
#define SWZ(row, ch) ((row) * 128 + ((((uint32_t)(ch)) << 4) ^ ((((uint32_t)(row)) & 7) << 4)))

// ---------------------------------------------------------------------------
// One-time f32 -> f16 conversion: x, {Wq|Wk|Wv} packed, Wo, biases.
// ---------------------------------------------------------------------------
#define XCH   (NB * SEQ * DM / 8)        // 524288 16B-chunks
#define WCH   (DM * DM / 8)              // 32768 per weight
__global__ __launch_bounds__(256) void convert_all(
    const float* __restrict__ x,
    const float* __restrict__ Wq, const float* __restrict__ Wk,
    const float* __restrict__ Wv, const float* __restrict__ Wo,
    const float* __restrict__ bq, const float* __restrict__ bk,
    const float* __restrict__ bv)
{
    int idx = blockIdx.x * 256 + threadIdx.x;
    if (idx < XCH) {
        *(uint4*)(g_Xh + (size_t)idx * 8) = ld_chunk(x + (size_t)idx * 8);
    } else if (idx < XCH + 3 * WCH) {
        int c  = idx - XCH;
        int j  = c >> 15;                // weight select
        int cc = c & (WCH - 1);
        int k  = cc >> 6, n8 = cc & 63;
        const float* W = (j == 0) ? Wq : ((j == 1) ? Wk : Wv);
        *(uint4*)(g_Wqkv + (size_t)k * 1536 + j * 512 + n8 * 8) =
            ld_chunk(W + (size_t)k * 512 + n8 * 8);
    } else if (idx < XCH + 4 * WCH) {
        int cc = idx - XCH - 3 * WCH;
        int k = cc >> 6, n8 = cc & 63;
        *(uint4*)(g_Woh + (size_t)k * 512 + n8 * 8) =
            ld_chunk(Wo + (size_t)k * 512 + n8 * 8);
    } else if (idx < XCH + 4 * WCH + 3 * DM) {
        int n = idx - XCH - 4 * WCH;
        g_bqkv[n] = (n < 512) ? bq[n] : ((n < 1024) ? bk[n - 512] : bv[n - 1024]);
    }
}

// ---------------------------------------------------------------------------
// Unified f16 GEMM, cp.async double-buffered.
// C[M, NW] = A[M,512] @ W[512,NW] + bias.  Block 128x128, 256 thr, 8 warps
// (2M x 4N), warp tile 64x32.  SMEM/stage: As 16K + Bs 2x8K subtiles = 32K.
// MODE 0 (NW=1536): split-head f16 scatter into q/k/v.  MODE 1: f32 row-major.
// ---------------------------------------------------------------------------
template <int NW, int MODE>
__global__ __launch_bounds__(256, 2) void gemm_f16(
    const __half* __restrict__ A, const __half* __restrict__ W,
    const float* __restrict__ bias,
    __half* __restrict__ oq, __half* __restrict__ ok_, __half* __restrict__ ov,
    float* __restrict__ Cf)
{
    extern __shared__ __align__(128) unsigned char smg[];   // 2 x 32KB
    const uint32_t SB = smem_u32(smg);

    const int tid = threadIdx.x, lane = tid & 31, w = tid >> 5;
    const int g = lane >> 2, t = lane & 3;
    const int wm = w & 1, wn = w >> 1;
    const int m0 = blockIdx.y * 128, n0 = blockIdx.x * 128;

    float acc[4][4][4] = {};

    // stage loader: As[row<128][ch<8], Bs sub (c>>3) [row<64][c&7]
    #define GEMM_ISSUE(K0, SOFF)                                               \
        do {                                                                   \
            _Pragma("unroll")                                                  \
            for (int i = 0; i < 4; i++) {                                      \
                int idx = tid + i * 256;                                       \
                int row = idx >> 3, ch = idx & 7;                              \
                cp_async16(SB + (SOFF) + SWZ(row, ch),                         \
                           A + (size_t)(m0 + row) * DM + (K0) + ch * 8);       \
            }                                                                  \
            _Pragma("unroll")                                                  \
            for (int i = 0; i < 4; i++) {                                      \
                int idx = tid + i * 256;                                       \
                int row = idx >> 4, c = idx & 15;                              \
                cp_async16(SB + (SOFF) + 16384 + (uint32_t)(c >> 3) * 8192 +   \
                               SWZ(row, c & 7),                                \
                           W + (size_t)((K0) + row) * NW + n0 + c * 8);        \
            }                                                                  \
        } while (0)

    GEMM_ISSUE(0, 0u);
    cp_commit();

    const uint32_t sw = ((uint32_t)(lane & 7)) << 4;
    const int a_kch = lane >> 4;
    const int b_rl  = ((lane >> 3) & 1) * 8 + (lane & 7);
    const int b_ch0 = (wn & 1) * 4 + (lane >> 4);

    for (int kt = 0; kt < DM / 64; kt++) {
        cp_wait<0>();
        __syncthreads();
        if (kt + 1 < DM / 64) {
            GEMM_ISSUE((kt + 1) * 64, (uint32_t)((kt + 1) & 1) * 32768u);
            cp_commit();
        }
        const uint32_t AOs = SB + (uint32_t)(kt & 1) * 32768u;
        const uint32_t BOs = AOs + 16384 + (uint32_t)(wn >> 1) * 8192;

        #pragma unroll
        for (int ks = 0; ks < 4; ks++) {
            uint32_t a[4][4];
            #pragma unroll
            for (int mt = 0; mt < 4; mt++) {
                int ar = wm * 64 + mt * 16 + (lane & 15);
                ldsm_x4(a[mt], AOs + (uint32_t)ar * 128 +
                        ((((uint32_t)(2 * ks + a_kch)) << 4) ^ sw));
            }
            #pragma unroll
            for (int np = 0; np < 2; np++) {
                uint32_t bv4[4];
                int br = ks * 16 + b_rl;
                ldsm_x4_t(bv4, BOs + (uint32_t)br * 128 +
                          ((((uint32_t)(b_ch0 + np * 2)) << 4) ^ sw));
                #pragma unroll
                for (int mt = 0; mt < 4; mt++) {
                    mma_f16(acc[mt][np * 2],     a[mt], bv4[0], bv4[1]);
                    mma_f16(acc[mt][np * 2 + 1], a[mt], bv4[2], bv4[3]);
                }
            }
        }
    }
    #undef GEMM_ISSUE

    // epilogue
    if (MODE == 0) {
        const int wsel = n0 >> 9;   // uniform per block (128 | 512)
        __half* __restrict__ osel = (wsel == 0) ? oq : ((wsel == 1) ? ok_ : ov);
        #pragma unroll
        for (int mt = 0; mt < 4; mt++)
            #pragma unroll
            for (int nt = 0; nt < 4; nt++)
                #pragma unroll
                for (int eh = 0; eh < 2; eh++) {
                    int m  = m0 + wm * 64 + mt * 16 + g + eh * 8;
                    int ng = n0 + wn * 32 + nt * 8 + 2 * t;
                    float v0 = acc[mt][nt][eh * 2]     + bias[ng];
                    float v1 = acc[mt][nt][eh * 2 + 1] + bias[ng + 1];
                    int nl = ng & 511;
                    int b = m >> 11, s = m & (SEQ - 1);
                    int h = nl >> 6, d = nl & (DH - 1);
                    *(__half2*)&osel[(((size_t)(b * NH + h)) * SEQ + s) * DH + d] =
                        __floats2half2_rn(v0, v1);
                }
    } else {
        #pragma unroll
        for (int mt = 0; mt < 4; mt++)
            #pragma unroll
            for (int nt = 0; nt < 4; nt++)
                #pragma unroll
                for (int e = 0; e < 4; e++) {
                    int m  = m0 + wm * 64 + mt * 16 + g + ((e >> 1) ? 8 : 0);
                    int ng = n0 + wn * 32 + nt * 8 + 2 * t + (e & 1);
                    Cf[(size_t)m * DM + ng] = acc[mt][nt][e] + bias[ng];
                }
    }
}

// ---------------------------------------------------------------------------
// Flash attention: 128-row Q tile, 64-key tiles, cp.async double-buffered K/V.
// 256 threads, 8 warps (4M x 2N), warp tile 32x32 for S and O.
// SMEM: Q 16K | KV stage0 16K | KV stage1 16K | P 16K | pm/ps 2K = 67584 B.
// ---------------------------------------------------------------------------
__global__ __launch_bounds__(256, 2) void attn_f16_v4()
{
    extern __shared__ __align__(128) unsigned char sma[];
    const uint32_t SB = smem_u32(sma);
    const uint32_t QO = SB;
    const uint32_t PO = SB + 49152;
    float* pm = (float*)(sma + 65536);   // [2][128]
    float* ps = (float*)(sma + 66560);   // [2][128]

    const int tid = threadIdx.x, lane = tid & 31, w = tid >> 5;
    const int g = lane >> 2, t = lane & 3;
    const int wm = w & 3, wn = w >> 2;
    const int bh = blockIdx.y;
    const int q0 = blockIdx.x * 128;

    const __half* __restrict__ Qg = g_Q + (size_t)bh * SEQ * DH;
    const __half* __restrict__ Kg = g_K + (size_t)bh * SEQ * DH;
    const __half* __restrict__ Vg = g_V + (size_t)bh * SEQ * DH;

    const float scale = 0.04419417382415922f;  // 1/sqrt(512)

    // K/V stage loader: K at 16384 + s*16384, V at +8192
    #define KV_ISSUE(C0, S)                                                    \
        do {                                                                   \
            uint32_t kb_ = SB + 16384u + (uint32_t)(S) * 16384u;               \
            _Pragma("unroll")                                                  \
            for (int i = 0; i < 2; i++) {                                      \
                int idx = tid + i * 256;                                       \
                int row = idx >> 3, ch = idx & 7;                              \
                cp_async16(kb_ + SWZ(row, ch),                                 \
                           Kg + (size_t)((C0) + row) * DH + ch * 8);           \
            }                                                                  \
            _Pragma("unroll")                                                  \
            for (int i = 0; i < 2; i++) {                                      \
                int idx = tid + i * 256;                                       \
                int row = idx >> 3, ch = idx & 7;                              \
                cp_async16(kb_ + 8192 + SWZ(row, ch),                          \
                           Vg + (size_t)((C0) + row) * DH + ch * 8);           \
            }                                                                  \
        } while (0)

    // Q loads + KV stage 0, one group
    #pragma unroll
    for (int i = 0; i < 4; i++) {
        int idx = tid + i * 256;
        int row = idx >> 3, ch = idx & 7;
        cp_async16(QO + SWZ(row, ch), Qg + (size_t)(q0 + row) * DH + ch * 8);
    }
    KV_ISSUE(0, 0);
    cp_commit();

    // lane-fixed addressing (all swizzle XORs equal (lane&7)<<4)
    const uint32_t sw = ((uint32_t)(lane & 7)) << 4;
    const uint32_t a_off0 = (uint32_t)(wm * 32 + (lane & 15)) * 128;
    const int a_kch = lane >> 4;
    const uint32_t k_row = (uint32_t)(wn * 32 + (lane >> 4) * 8 + (lane & 7));
    const int kch = (lane >> 3) & 1;
    const int vrow_off = ((lane >> 3) & 1) * 8 + (lane & 7);
    const int v_ch = wn * 4 + (lane >> 4);
    const uint32_t s_off0 = PO + (uint32_t)(wm * 32 + ((lane >> 3) & 1) * 8 + (lane & 7)) * 128;
    const int s_ch0 = wn * 4 + (lane >> 4);

    const int r00 = wm * 32 + g;   // rows owned: r00 + mt*16 + h*8
    float mrow[2][2] = {{-INFINITY, -INFINITY}, {-INFINITY, -INFINITY}};
    float lrow[2][2] = {{0.0f, 0.0f}, {0.0f, 0.0f}};
    float o[2][4][4] = {};

    for (int kt = 0; kt < SEQ / 64; kt++) {
        cp_wait<0>();
        __syncthreads();
        if (kt + 1 < SEQ / 64) {
            KV_ISSUE((kt + 1) * 64, (kt + 1) & 1);
            cp_commit();
        }
        const uint32_t KB = SB + 16384u + (uint32_t)(kt & 1) * 16384u;
        const uint32_t VB = KB + 8192u;
        const uint32_t k_off0 = KB + k_row * 128;

        // ---- S = Q K^T : warp tile 32x32, k = 64 ----
        float s[2][4][4] = {};
        #pragma unroll
        for (int ks = 0; ks < 4; ks++) {
            uint32_t ck = ((uint32_t)(2 * ks + kch)) << 4;
            uint32_t bf[2][4];
            ldsm_x4(bf[0], k_off0 + (ck ^ sw));
            ldsm_x4(bf[1], k_off0 + 16 * 128 + (ck ^ sw));
            #pragma unroll
            for (int mt = 0; mt < 2; mt++) {
                uint32_t a[4];
                ldsm_x4(a, QO + a_off0 + (uint32_t)(mt * 16) * 128 +
                        ((((uint32_t)(2 * ks + a_kch)) << 4) ^ sw));
                mma_f16(s[mt][0], a, bf[0][0], bf[0][1]);
                mma_f16(s[mt][1], a, bf[0][2], bf[0][3]);
                mma_f16(s[mt][2], a, bf[1][0], bf[1][1]);
                mma_f16(s[mt][3], a, bf[1][2], bf[1][3]);
            }
        }

        // ---- online softmax: partial max ----
        #pragma unroll
        for (int mt = 0; mt < 2; mt++) {
            float mx0 = -INFINITY, mx1 = -INFINITY;
            #pragma unroll
            for (int nt = 0; nt < 4; nt++) {
                #pragma unroll
                for (int e = 0; e < 4; e++) s[mt][nt][e] *= scale;
                mx0 = fmaxf(mx0, fmaxf(s[mt][nt][0], s[mt][nt][1]));
                mx1 = fmaxf(mx1, fmaxf(s[mt][nt][2], s[mt][nt][3]));
            }
            mx0 = fmaxf(mx0, __shfl_xor_sync(0xffffffffu, mx0, 1));
            mx0 = fmaxf(mx0, __shfl_xor_sync(0xffffffffu, mx0, 2));
            mx1 = fmaxf(mx1, __shfl_xor_sync(0xffffffffu, mx1, 1));
            mx1 = fmaxf(mx1, __shfl_xor_sync(0xffffffffu, mx1, 2));
            if (t == 0) {
                pm[wn * 128 + r00 + mt * 16]     = mx0;
                pm[wn * 128 + r00 + mt * 16 + 8] = mx1;
            }
        }
        __syncthreads();

        float mn[2][2];
        #pragma unroll
        for (int mt = 0; mt < 2; mt++)
            #pragma unroll
            for (int h = 0; h < 2; h++) {
                int r = r00 + mt * 16 + h * 8;
                mn[mt][h] = fmaxf(mrow[mt][h], fmaxf(pm[r], pm[128 + r]));
            }

        // ---- exp, partial sums, P -> SMEM (stmatrix) ----
        #pragma unroll
        for (int mt = 0; mt < 2; mt++) {
            float rs0 = 0.0f, rs1 = 0.0f;
            #pragma unroll
            for (int nt = 0; nt < 4; nt++) {
                s[mt][nt][0] = __expf(s[mt][nt][0] - mn[mt][0]);
                s[mt][nt][1] = __expf(s[mt][nt][1] - mn[mt][0]);
                s[mt][nt][2] = __expf(s[mt][nt][2] - mn[mt][1]);
                s[mt][nt][3] = __expf(s[mt][nt][3] - mn[mt][1]);
                rs0 += s[mt][nt][0] + s[mt][nt][1];
                rs1 += s[mt][nt][2] + s[mt][nt][3];
            }
            #pragma unroll
            for (int np2 = 0; np2 < 2; np2++) {
                uint32_t h0 = h2u(__floats2half2_rn(s[mt][np2 * 2][0],     s[mt][np2 * 2][1]));
                uint32_t h1 = h2u(__floats2half2_rn(s[mt][np2 * 2][2],     s[mt][np2 * 2][3]));
                uint32_t h2_ = h2u(__floats2half2_rn(s[mt][np2 * 2 + 1][0], s[mt][np2 * 2 + 1][1]));
                uint32_t h3 = h2u(__floats2half2_rn(s[mt][np2 * 2 + 1][2], s[mt][np2 * 2 + 1][3]));
                stsm_x4(s_off0 + (uint32_t)(mt * 16) * 128 +
                        ((((uint32_t)(s_ch0 + np2 * 2)) << 4) ^ sw),
                        h0, h1, h2_, h3);
            }
            rs0 += __shfl_xor_sync(0xffffffffu, rs0, 1);
            rs0 += __shfl_xor_sync(0xffffffffu, rs0, 2);
            rs1 += __shfl_xor_sync(0xffffffffu, rs1, 1);
            rs1 += __shfl_xor_sync(0xffffffffu, rs1, 2);
            if (t == 0) {
                ps[wn * 128 + r00 + mt * 16]     = rs0;
                ps[wn * 128 + r00 + mt * 16 + 8] = rs1;
            }
        }
        __syncthreads();

        // ---- update row state, rescale O ----
        float al[2][2];
        #pragma unroll
        for (int mt = 0; mt < 2; mt++)
            #pragma unroll
            for (int h = 0; h < 2; h++) {
                int r = r00 + mt * 16 + h * 8;
                al[mt][h] = __expf(mrow[mt][h] - mn[mt][h]);
                mrow[mt][h] = mn[mt][h];
                lrow[mt][h] = lrow[mt][h] * al[mt][h] + ps[r] + ps[128 + r];
            }
        #pragma unroll
        for (int mt = 0; mt < 2; mt++)
            #pragma unroll
            for (int nt = 0; nt < 4; nt++) {
                o[mt][nt][0] *= al[mt][0]; o[mt][nt][1] *= al[mt][0];
                o[mt][nt][2] *= al[mt][1]; o[mt][nt][3] *= al[mt][1];
            }

        // ---- O += P V : warp tile 32x32, k = 64 keys ----
        #pragma unroll
        for (int ks = 0; ks < 4; ks++) {
            uint32_t bf[2][4];
            #pragma unroll
            for (int np = 0; np < 2; np++)
                ldsm_x4_t(bf[np], VB + (uint32_t)(ks * 16 + vrow_off) * 128 +
                          ((((uint32_t)(v_ch + np * 2)) << 4) ^ sw));
            #pragma unroll
            for (int mt = 0; mt < 2; mt++) {
                uint32_t a[4];
                ldsm_x4(a, PO + a_off0 + (uint32_t)(mt * 16) * 128 +
                        ((((uint32_t)(2 * ks + a_kch)) << 4) ^ sw));
                mma_f16(o[mt][0], a, bf[0][0], bf[0][1]);
                mma_f16(o[mt][1], a, bf[0][2], bf[0][3]);
                mma_f16(o[mt][2], a, bf[1][0], bf[1][1]);
                mma_f16(o[mt][3], a, bf[1][2], bf[1][3]);
            }
        }
    }
    #undef KV_ISSUE

    // ---- epilogue: normalize, write merged-head layout (f16) ----
    const int b = bh >> 3, h = bh & 7;
    #pragma unroll
    for (int mt = 0; mt < 2; mt++) {
        float inv0 = 1.0f / lrow[mt][0];
        float inv1 = 1.0f / lrow[mt][1];
        int row0 = q0 + r00 + mt * 16;
        #pragma unroll
        for (int nt = 0; nt < 4; nt++) {
            int col = h * DH + wn * 32 + nt * 8 + 2 * t;
            size_t i0 = ((size_t)(b * SEQ + row0)) * DM + col;
            size_t i1 = ((size_t)(b * SEQ + row0 + 8)) * DM + col;
            *(__half2*)&g_ATT[i0] = __floats2half2_rn(o[mt][nt][0] * inv0, o[mt][nt][1] * inv0);
            *(__half2*)&g_ATT[i1] = __floats2half2_rn(o[mt][nt][2] * inv1, o[mt][nt][3] * inv1);
        }
    }
}

// ---------------------------------------------------------------------------
extern "C" void kernel_launch(void* const* d_in, const int* in_sizes, int n_in,
                              void* d_out, int out_size)
{
    (void)in_sizes; (void)n_in; (void)out_size;
    const float* x  = (const float*)d_in[0];
    const float* Wq = (const float*)d_in[1];
    const float* bq = (const float*)d_in[2];
    const float* Wk = (const float*)d_in[3];
    const float* bk = (const float*)d_in[4];
    const float* Wv = (const float*)d_in[5];
    const float* bv = (const float*)d_in[6];
    const float* Wo = (const float*)d_in[7];
    const float* bo = (const float*)d_in[8];

    __half *qp, *kp, *vp, *ap, *xhp, *wqkvp, *wohp;
    float* bqkvp;
    cudaGetSymbolAddress((void**)&qp, g_Q);
    cudaGetSymbolAddress((void**)&kp, g_K);
    cudaGetSymbolAddress((void**)&vp, g_V);
    cudaGetSymbolAddress((void**)&ap, g_ATT);
    cudaGetSymbolAddress((void**)&xhp, g_Xh);
    cudaGetSymbolAddress((void**)&wqkvp, g_Wqkv);
    cudaGetSymbolAddress((void**)&wohp, g_Woh);
    cudaGetSymbolAddress((void**)&bqkvp, g_bqkv);

    static bool attr_set = false;
    if (!attr_set) {
        cudaFuncSetAttribute(gemm_f16<1536, 0>,
                             cudaFuncAttributeMaxDynamicSharedMemorySize, 65536);
        cudaFuncSetAttribute(gemm_f16<512, 1>,
                             cudaFuncAttributeMaxDynamicSharedMemorySize, 65536);
        cudaFuncSetAttribute(attn_f16_v4,
                             cudaFuncAttributeMaxDynamicSharedMemorySize, 67584);
        attr_set = true;
    }

    int conv_chunks = XCH + 4 * WCH + 3 * DM;
    convert_all<<<(conv_chunks + 255) / 256, 256>>>(x, Wq, Wk, Wv, Wo, bq, bk, bv);

    gemm_f16<1536, 0><<<dim3(12, 64), 256, 65536>>>(
        xhp, wqkvp, bqkvp, qp, kp, vp, nullptr);

    attn_f16_v4<<<dim3(SEQ / 128, NB * NH), 256, 67584>>>();

    gemm_f16<512, 1><<<dim3(4, 64), 256, 65536>>>(
        ap, wohp, bo, nullptr, nullptr, nullptr, (float*)d_out);
}

// round 10
// speedup vs baseline: 7.8428x; 1.1793x over previous
#include <cuda_runtime.h>
#include <cuda_fp16.h>
#include <math.h>
#include <stdint.h>

#define NB 4
#define SEQ 2048
#define DM 512
#define NH 8
#define DH 64

// f16 intermediates / converted operands (allocation-free rule)
__device__ __half g_Q[NB * NH * SEQ * DH];
__device__ __half g_K[NB * NH * SEQ * DH];
__device__ __half g_V[NB * NH * SEQ * DH];
__device__ __half g_ATT[NB * SEQ * DM];
__device__ __half g_Xh[NB * SEQ * DM];
__device__ __half g_Wqkv[DM * 3 * DM];   // [512][1536]: (scale*Wq)|Wk|Wv columns
__device__ __half g_Woh[DM * DM];
__device__ float  g_bqkv[3 * DM];        // (scale*bq)|bk|bv

// ---------------------------------------------------------------------------
// helpers
// ---------------------------------------------------------------------------
__device__ __forceinline__ uint32_t smem_u32(const void* p) {
    uint32_t a;
    asm("{ .reg .u64 t; cvta.to.shared.u64 t, %1; cvt.u32.u64 %0, t; }"
        : "=r"(a) : "l"(p));
    return a;
}
__device__ __forceinline__ void ldsm_x4(uint32_t r[4], uint32_t addr) {
    asm volatile("ldmatrix.sync.aligned.m8n8.x4.shared.b16 {%0,%1,%2,%3}, [%4];"
                 : "=r"(r[0]), "=r"(r[1]), "=r"(r[2]), "=r"(r[3]) : "r"(addr));
}
__device__ __forceinline__ void ldsm_x4_t(uint32_t r[4], uint32_t addr) {
    asm volatile("ldmatrix.sync.aligned.m8n8.x4.trans.shared.b16 {%0,%1,%2,%3}, [%4];"
                 : "=r"(r[0]), "=r"(r[1]), "=r"(r[2]), "=r"(r[3]) : "r"(addr));
}
__device__ __forceinline__ void mma_f16(float d[4], const uint32_t a[4],
                                        uint32_t b0, uint32_t b1) {
    asm volatile(
        "mma.sync.aligned.m16n8k16.row.col.f32.f16.f16.f32 "
        "{%0,%1,%2,%3}, {%4,%5,%6,%7}, {%8,%9}, {%0,%1,%2,%3};\n"
        : "+f"(d[0]), "+f"(d[1]), "+f"(d[2]), "+f"(d[3])
        : "r"(a[0]), "r"(a[1]), "r"(a[2]), "r"(a[3]), "r"(b0), "r"(b1));
}
__device__ __forceinline__ void cp_async16(uint32_t saddr, const void* g) {
    asm volatile("cp.async.cg.shared.global [%0], [%1], 16;"
                 :: "r"(saddr), "l"(g) : "memory");
}
__device__ __forceinline__ void cp_commit() {
    asm volatile("cp.async.commit_group;" ::: "memory");
}
template <int N>
__device__ __forceinline__ void cp_wait() {
    asm volatile("cp.async.wait_group %0;" :: "n"(N) : "memory");
}
__device__ __forceinline__ uint32_t h2u(__half2 h) {
    return *reinterpret_cast<uint32_t*>(&h);
}
__device__ __forceinline__ uint4 ld_chunk(const float* p) {
    float4 v0 = *(const float4*)p;
    float4 v1 = *(const float4*)(p + 4);
    return make_uint4(h2u(__floats2half2_rn(v0.x, v0.y)),
                      h2u(__floats2half2_rn(v0.z, v0.w)),
                      h2u(__floats2half2_rn(v1.x, v1.y)),
                      h2u(__floats2half2_rn(v1.z, v1.w)));
}
__device__ __forceinline__ uint4 ld_chunk_s(const float* p, float sc) {
    float4 v0 = *(const float4*)p;
    float4 v1 = *(const float4*)(p + 4);
    return make_uint4(h2u(__floats2half2_rn(v0.x * sc, v0.y * sc)),
                      h2u(__floats2half2_rn(v0.z * sc, v0.w * sc)),
                      h2u(__floats2half2_rn(v1.x * sc, v1.y * sc)),
                      h2u(__floats2half2_rn(v1.z * sc, v1.w * sc)));
}

// swizzled byte offset within a 64-col f16 tile (128B rows)
#define SWZ(row, ch) ((row) * 128 + ((((uint32_t)(ch)) << 4) ^ ((((uint32_t)(row)) & 7) << 4)))

#define ATT_SCALE 0.04419417382415922f   // 1/sqrt(512)

// ---------------------------------------------------------------------------
// One-time f32 -> f16 conversion: x, {scale*Wq|Wk|Wv} packed, Wo, biases.
// ---------------------------------------------------------------------------
#define XCH   (NB * SEQ * DM / 8)        // 524288 16B-chunks
#define WCH   (DM * DM / 8)              // 32768 per weight
__global__ __launch_bounds__(256) void convert_all(
    const float* __restrict__ x,
    const float* __restrict__ Wq, const float* __restrict__ Wk,
    const float* __restrict__ Wv, const float* __restrict__ Wo,
    const float* __restrict__ bq, const float* __restrict__ bk,
    const float* __restrict__ bv)
{
    int idx = blockIdx.x * 256 + threadIdx.x;
    if (idx < XCH) {
        *(uint4*)(g_Xh + (size_t)idx * 8) = ld_chunk(x + (size_t)idx * 8);
    } else if (idx < XCH + 3 * WCH) {
        int c  = idx - XCH;
        int j  = c >> 15;                // weight select
        int cc = c & (WCH - 1);
        int k  = cc >> 6, n8 = cc & 63;
        const float* W = (j == 0) ? Wq : ((j == 1) ? Wk : Wv);
        float sc = (j == 0) ? ATT_SCALE : 1.0f;
        *(uint4*)(g_Wqkv + (size_t)k * 1536 + j * 512 + n8 * 8) =
            ld_chunk_s(W + (size_t)k * 512 + n8 * 8, sc);
    } else if (idx < XCH + 4 * WCH) {
        int cc = idx - XCH - 3 * WCH;
        int k = cc >> 6, n8 = cc & 63;
        *(uint4*)(g_Woh + (size_t)k * 512 + n8 * 8) =
            ld_chunk(Wo + (size_t)k * 512 + n8 * 8);
    } else if (idx < XCH + 4 * WCH + 3 * DM) {
        int n = idx - XCH - 4 * WCH;
        g_bqkv[n] = (n < 512) ? bq[n] * ATT_SCALE
                              : ((n < 1024) ? bk[n - 512] : bv[n - 1024]);
    }
}

// ---------------------------------------------------------------------------
// Unified f16 GEMM, cp.async double-buffered.
// C[M, NW] = A[M,512] @ W[512,NW] + bias.  Block 128x128, 256 thr, 8 warps
// (2M x 4N), warp tile 64x32.  MODE 0: split-head f16 scatter; 1: f32 rowmajor.
// ---------------------------------------------------------------------------
template <int NW, int MODE>
__global__ __launch_bounds__(256, 2) void gemm_f16(
    const __half* __restrict__ A, const __half* __restrict__ W,
    const float* __restrict__ bias,
    __half* __restrict__ oq, __half* __restrict__ ok_, __half* __restrict__ ov,
    float* __restrict__ Cf)
{
    extern __shared__ __align__(128) unsigned char smg[];   // 2 x 32KB
    const uint32_t SB = smem_u32(smg);

    const int tid = threadIdx.x, lane = tid & 31, w = tid >> 5;
    const int g = lane >> 2, t = lane & 3;
    const int wm = w & 1, wn = w >> 1;
    const int m0 = blockIdx.y * 128, n0 = blockIdx.x * 128;

    float acc[4][4][4] = {};

    #define GEMM_ISSUE(K0, SOFF)                                               \
        do {                                                                   \
            _Pragma("unroll")                                                  \
            for (int i = 0; i < 4; i++) {                                      \
                int idx = tid + i * 256;                                       \
                int row = idx >> 3, ch = idx & 7;                              \
                cp_async16(SB + (SOFF) + SWZ(row, ch),                         \
                           A + (size_t)(m0 + row) * DM + (K0) + ch * 8);       \
            }                                                                  \
            _Pragma("unroll")                                                  \
            for (int i = 0; i < 4; i++) {                                      \
                int idx = tid + i * 256;                                       \
                int row = idx >> 4, c = idx & 15;                              \
                cp_async16(SB + (SOFF) + 16384 + (uint32_t)(c >> 3) * 8192 +   \
                               SWZ(row, c & 7),                                \
                           W + (size_t)((K0) + row) * NW + n0 + c * 8);        \
            }                                                                  \
        } while (0)

    GEMM_ISSUE(0, 0u);
    cp_commit();

    const uint32_t sw = ((uint32_t)(lane & 7)) << 4;
    const int a_kch = lane >> 4;
    const int b_rl  = ((lane >> 3) & 1) * 8 + (lane & 7);
    const int b_ch0 = (wn & 1) * 4 + (lane >> 4);

    for (int kt = 0; kt < DM / 64; kt++) {
        cp_wait<0>();
        __syncthreads();
        if (kt + 1 < DM / 64) {
            GEMM_ISSUE((kt + 1) * 64, (uint32_t)((kt + 1) & 1) * 32768u);
            cp_commit();
        }
        const uint32_t AOs = SB + (uint32_t)(kt & 1) * 32768u;
        const uint32_t BOs = AOs + 16384 + (uint32_t)(wn >> 1) * 8192;

        #pragma unroll
        for (int ks = 0; ks < 4; ks++) {
            uint32_t a[4][4];
            #pragma unroll
            for (int mt = 0; mt < 4; mt++) {
                int ar = wm * 64 + mt * 16 + (lane & 15);
                ldsm_x4(a[mt], AOs + (uint32_t)ar * 128 +
                        ((((uint32_t)(2 * ks + a_kch)) << 4) ^ sw));
            }
            #pragma unroll
            for (int np = 0; np < 2; np++) {
                uint32_t bv4[4];
                int br = ks * 16 + b_rl;
                ldsm_x4_t(bv4, BOs + (uint32_t)br * 128 +
                          ((((uint32_t)(b_ch0 + np * 2)) << 4) ^ sw));
                #pragma unroll
                for (int mt = 0; mt < 4; mt++) {
                    mma_f16(acc[mt][np * 2],     a[mt], bv4[0], bv4[1]);
                    mma_f16(acc[mt][np * 2 + 1], a[mt], bv4[2], bv4[3]);
                }
            }
        }
    }
    #undef GEMM_ISSUE

    if (MODE == 0) {
        const int wsel = n0 >> 9;   // uniform per block
        __half* __restrict__ osel = (wsel == 0) ? oq : ((wsel == 1) ? ok_ : ov);
        #pragma unroll
        for (int mt = 0; mt < 4; mt++)
            #pragma unroll
            for (int nt = 0; nt < 4; nt++)
                #pragma unroll
                for (int eh = 0; eh < 2; eh++) {
                    int m  = m0 + wm * 64 + mt * 16 + g + eh * 8;
                    int ng = n0 + wn * 32 + nt * 8 + 2 * t;
                    float v0 = acc[mt][nt][eh * 2]     + bias[ng];
                    float v1 = acc[mt][nt][eh * 2 + 1] + bias[ng + 1];
                    int nl = ng & 511;
                    int b = m >> 11, s = m & (SEQ - 1);
                    int h = nl >> 6, d = nl & (DH - 1);
                    *(__half2*)&osel[(((size_t)(b * NH + h)) * SEQ + s) * DH + d] =
                        __floats2half2_rn(v0, v1);
                }
    } else {
        #pragma unroll
        for (int mt = 0; mt < 4; mt++)
            #pragma unroll
            for (int nt = 0; nt < 4; nt++)
                #pragma unroll
                for (int e = 0; e < 4; e++) {
                    int m  = m0 + wm * 64 + mt * 16 + g + ((e >> 1) ? 8 : 0);
                    int ng = n0 + wn * 32 + nt * 8 + 2 * t + (e & 1);
                    Cf[(size_t)m * DM + ng] = acc[mt][nt][e] + bias[ng];
                }
    }
}

// ---------------------------------------------------------------------------
// Flash attention v5: register-resident P (FA2 style).
// Block = 128 q-rows x one b*h, 256 threads, 8 warps; each warp owns 16 full
// rows x all 64 keys. Softmax is warp-local (quad shuffles only). P stays in
// registers: C-fragments of S repack directly into A-fragments for PV.
// SMEM: Q 16K | KV stage0 16K | KV stage1 16K = 48 KB. One sync per tile.
// ---------------------------------------------------------------------------
__global__ __launch_bounds__(256, 2) void attn_f16_v5()
{
    extern __shared__ __align__(128) unsigned char sma[];
    const uint32_t SB = smem_u32(sma);
    const uint32_t QO = SB;

    const int tid = threadIdx.x, lane = tid & 31, w = tid >> 5;
    const int g = lane >> 2, t = lane & 3;
    const int bh = blockIdx.y;
    const int q0 = blockIdx.x * 128;

    const __half* __restrict__ Qg = g_Q + (size_t)bh * SEQ * DH;
    const __half* __restrict__ Kg = g_K + (size_t)bh * SEQ * DH;
    const __half* __restrict__ Vg = g_V + (size_t)bh * SEQ * DH;

    #define KV_ISSUE(C0, S)                                                    \
        do {                                                                   \
            uint32_t kb_ = SB + 16384u + (uint32_t)(S) * 16384u;               \
            _Pragma("unroll")                                                  \
            for (int i = 0; i < 2; i++) {                                      \
                int idx = tid + i * 256;                                       \
                int row = idx >> 3, ch = idx & 7;                              \
                cp_async16(kb_ + SWZ(row, ch),                                 \
                           Kg + (size_t)((C0) + row) * DH + ch * 8);           \
            }                                                                  \
            _Pragma("unroll")                                                  \
            for (int i = 0; i < 2; i++) {                                      \
                int idx = tid + i * 256;                                       \
                int row = idx >> 3, ch = idx & 7;                              \
                cp_async16(kb_ + 8192 + SWZ(row, ch),                          \
                           Vg + (size_t)((C0) + row) * DH + ch * 8);           \
            }                                                                  \
        } while (0)

    // Q (128x64) + KV stage 0
    #pragma unroll
    for (int i = 0; i < 4; i++) {
        int idx = tid + i * 256;
        int row = idx >> 3, ch = idx & 7;
        cp_async16(QO + SWZ(row, ch), Qg + (size_t)(q0 + row) * DH + ch * 8);
    }
    KV_ISSUE(0, 0);
    cp_commit();

    const uint32_t sw = ((uint32_t)(lane & 7)) << 4;
    const int a_kch = lane >> 4;
    const int kch   = (lane >> 3) & 1;
    const uint32_t k_row = (uint32_t)((lane >> 4) * 8 + (lane & 7));   // + rb*16
    const int vrow_off = ((lane >> 3) & 1) * 8 + (lane & 7);           // + ks*16
    const int v_ch0 = lane >> 4;                                       // + np*2

    cp_wait<0>();
    __syncthreads();

    // Hoist Q A-fragments (tile-invariant): rows w*16 + (lane&15)
    uint32_t qf[4][4];
    {
        const uint32_t a_off0 = QO + (uint32_t)(w * 16 + (lane & 15)) * 128;
        #pragma unroll
        for (int ks = 0; ks < 4; ks++)
            ldsm_x4(qf[ks], a_off0 + ((((uint32_t)(2 * ks + a_kch)) << 4) ^ sw));
    }

    float m0 = -INFINITY, m1 = -INFINITY;   // rows g, g+8 of this warp's 16
    float l0 = 0.0f, l1 = 0.0f;
    float o[8][4] = {};

    for (int kt = 0; kt < SEQ / 64; kt++) {
        if (kt > 0) { cp_wait<0>(); __syncthreads(); }
        if (kt + 1 < SEQ / 64) {
            KV_ISSUE((kt + 1) * 64, (kt + 1) & 1);
            cp_commit();
        }
        const uint32_t KB = SB + 16384u + (uint32_t)(kt & 1) * 16384u;
        const uint32_t VB = KB + 8192u;
        const uint32_t k_off = KB + k_row * 128;

        // ---- S = Q K^T : 16 rows x 64 keys ----
        float s[8][4] = {};
        #pragma unroll
        for (int ks = 0; ks < 4; ks++) {
            uint32_t ck = ((uint32_t)(2 * ks + kch)) << 4;
            #pragma unroll
            for (int rb = 0; rb < 4; rb++) {
                uint32_t bf[4];
                ldsm_x4(bf, k_off + (uint32_t)(rb * 16) * 128 + (ck ^ sw));
                mma_f16(s[rb * 2],     qf[ks], bf[0], bf[1]);
                mma_f16(s[rb * 2 + 1], qf[ks], bf[2], bf[3]);
            }
        }

        // ---- warp-local online softmax (rows g / g+8, quad reduce) ----
        float mx0 = -INFINITY, mx1 = -INFINITY;
        #pragma unroll
        for (int j = 0; j < 8; j++) {
            mx0 = fmaxf(mx0, fmaxf(s[j][0], s[j][1]));
            mx1 = fmaxf(mx1, fmaxf(s[j][2], s[j][3]));
        }
        mx0 = fmaxf(mx0, __shfl_xor_sync(0xffffffffu, mx0, 1));
        mx0 = fmaxf(mx0, __shfl_xor_sync(0xffffffffu, mx0, 2));
        mx1 = fmaxf(mx1, __shfl_xor_sync(0xffffffffu, mx1, 1));
        mx1 = fmaxf(mx1, __shfl_xor_sync(0xffffffffu, mx1, 2));
        float mn0 = fmaxf(m0, mx0);
        float mn1 = fmaxf(m1, mx1);
        float al0 = __expf(m0 - mn0);
        float al1 = __expf(m1 - mn1);
        m0 = mn0; m1 = mn1;

        // exp, pack P straight into A-fragments, accumulate row sums
        uint32_t pf[4][4];
        float rs0 = 0.0f, rs1 = 0.0f;
        #pragma unroll
        for (int kc = 0; kc < 4; kc++) {
            #pragma unroll
            for (int jj = 0; jj < 2; jj++) {
                int j = kc * 2 + jj;
                float p0 = __expf(s[j][0] - mn0);
                float p1 = __expf(s[j][1] - mn0);
                float p2 = __expf(s[j][2] - mn1);
                float p3 = __expf(s[j][3] - mn1);
                rs0 += p0 + p1;
                rs1 += p2 + p3;
                pf[kc][jj * 2]     = h2u(__floats2half2_rn(p0, p1));
                pf[kc][jj * 2 + 1] = h2u(__floats2half2_rn(p2, p3));
            }
        }
        rs0 += __shfl_xor_sync(0xffffffffu, rs0, 1);
        rs0 += __shfl_xor_sync(0xffffffffu, rs0, 2);
        rs1 += __shfl_xor_sync(0xffffffffu, rs1, 1);
        rs1 += __shfl_xor_sync(0xffffffffu, rs1, 2);
        l0 = l0 * al0 + rs0;
        l1 = l1 * al1 + rs1;

        // rescale O
        #pragma unroll
        for (int j = 0; j < 8; j++) {
            o[j][0] *= al0; o[j][1] *= al0;
            o[j][2] *= al1; o[j][3] *= al1;
        }

        // ---- O += P V : P in registers, V from SMEM ----
        #pragma unroll
        for (int ks = 0; ks < 4; ks++) {
            #pragma unroll
            for (int np = 0; np < 4; np++) {
                uint32_t bf[4];
                ldsm_x4_t(bf, VB + (uint32_t)(ks * 16 + vrow_off) * 128 +
                          ((((uint32_t)(v_ch0 + np * 2)) << 4) ^ sw));
                mma_f16(o[np * 2],     pf[ks], bf[0], bf[1]);
                mma_f16(o[np * 2 + 1], pf[ks], bf[2], bf[3]);
            }
        }
    }
    #undef KV_ISSUE

    // ---- epilogue: normalize, write merged-head layout (f16) ----
    const int b = bh >> 3, h = bh & 7;
    float inv0 = 1.0f / l0;
    float inv1 = 1.0f / l1;
    int row0 = q0 + w * 16 + g;
    #pragma unroll
    for (int j = 0; j < 8; j++) {
        int col = h * DH + j * 8 + 2 * t;
        size_t i0 = ((size_t)(b * SEQ + row0)) * DM + col;
        size_t i1 = ((size_t)(b * SEQ + row0 + 8)) * DM + col;
        *(__half2*)&g_ATT[i0] = __floats2half2_rn(o[j][0] * inv0, o[j][1] * inv0);
        *(__half2*)&g_ATT[i1] = __floats2half2_rn(o[j][2] * inv1, o[j][3] * inv1);
    }
}

// ---------------------------------------------------------------------------
extern "C" void kernel_launch(void* const* d_in, const int* in_sizes, int n_in,
                              void* d_out, int out_size)
{
    (void)in_sizes; (void)n_in; (void)out_size;
    const float* x  = (const float*)d_in[0];
    const float* Wq = (const float*)d_in[1];
    const float* bq = (const float*)d_in[2];
    const float* Wk = (const float*)d_in[3];
    const float* bk = (const float*)d_in[4];
    const float* Wv = (const float*)d_in[5];
    const float* bv = (const float*)d_in[6];
    const float* Wo = (const float*)d_in[7];
    const float* bo = (const float*)d_in[8];

    __half *qp, *kp, *vp, *ap, *xhp, *wqkvp, *wohp;
    float* bqkvp;
    cudaGetSymbolAddress((void**)&qp, g_Q);
    cudaGetSymbolAddress((void**)&kp, g_K);
    cudaGetSymbolAddress((void**)&vp, g_V);
    cudaGetSymbolAddress((void**)&ap, g_ATT);
    cudaGetSymbolAddress((void**)&xhp, g_Xh);
    cudaGetSymbolAddress((void**)&wqkvp, g_Wqkv);
    cudaGetSymbolAddress((void**)&wohp, g_Woh);
    cudaGetSymbolAddress((void**)&bqkvp, g_bqkv);

    static bool attr_set = false;
    if (!attr_set) {
        cudaFuncSetAttribute(gemm_f16<1536, 0>,
                             cudaFuncAttributeMaxDynamicSharedMemorySize, 65536);
        cudaFuncSetAttribute(gemm_f16<512, 1>,
                             cudaFuncAttributeMaxDynamicSharedMemorySize, 65536);
        cudaFuncSetAttribute(attn_f16_v5,
                             cudaFuncAttributeMaxDynamicSharedMemorySize, 49152);
        attr_set = true;
    }

    int conv_chunks = XCH + 4 * WCH + 3 * DM;
    convert_all<<<(conv_chunks + 255) / 256, 256>>>(x, Wq, Wk, Wv, Wo, bq, bk, bv);

    gemm_f16<1536, 0><<<dim3(12, 64), 256, 65536>>>(
        xhp, wqkvp, bqkvp, qp, kp, vp, nullptr);

    attn_f16_v5<<<dim3(SEQ / 128, NB * NH), 256, 49152>>>();

    gemm_f16<512, 1><<<dim3(4, 64), 256, 65536>>>(
        ap, wohp, bo, nullptr, nullptr, nullptr, (float*)d_out);
}